// round 15
// baseline (speedup 1.0000x reference)
#include <cuda_runtime.h>
#include <math.h>

#define NN 50000
#define NE 800000
#define HD 64
#define NL 4

// Persistent state between launches (device globals: allocation-free).
__device__ float g_h[NN * HD];     // current node embedding
__device__ float g_e[NE * HD];     // current edge feature / message
__device__ float g_x[NN * 3];      // current coordinates
__device__ float g_agg[NN * HD];   // per-layer message aggregation
__device__ float g_dx[NN * 3];     // per-layer coordinate delta
__device__ float g_pa[NN * HD];    // h @ W1[0:64]   (row-half projection)
__device__ float g_pb[NN * HD];    // h @ W1[64:128] (col-half projection)

__device__ __forceinline__ float silu_f(float v) {
    return v / (1.0f + __expf(-v));
}

// ---- packed f32x2 helpers (Blackwell dual-rate fp32 path) ----
__device__ __forceinline__ unsigned long long pack2(float lo, float hi) {
    unsigned long long r;
    asm("mov.b64 %0, {%1, %2};" : "=l"(r) : "f"(lo), "f"(hi));
    return r;
}
__device__ __forceinline__ void unpack2(unsigned long long v, float& lo, float& hi) {
    asm("mov.b64 {%0, %1}, %2;" : "=f"(lo), "=f"(hi) : "l"(v));
}
__device__ __forceinline__ void ffma2(unsigned long long& d,
                                      unsigned long long a,
                                      unsigned long long b) {
    asm("fma.rn.f32x2 %0, %1, %2, %0;" : "+l"(d) : "l"(a), "l"(b));
}
__device__ __forceinline__ void red_add_v4(float* p, float4 v) {
    asm volatile("red.global.add.v4.f32 [%0], {%1, %2, %3, %4};"
                 :: "l"(p), "f"(v.x), "f"(v.y), "f"(v.z), "f"(v.w) : "memory");
}
__device__ __forceinline__ void red_add_f(float* p, float v) {
    asm volatile("red.global.add.f32 [%0], %1;" :: "l"(p), "f"(v) : "memory");
}
__device__ __forceinline__ void pair_bar(int id) {
    asm volatile("bar.sync %0, 64;" :: "r"(id) : "memory");
}

// ---------------------------------------------------------------------------
// Embedding kernels
// ---------------------------------------------------------------------------
__global__ void embed_node_kernel(const float* __restrict__ h_in,
                                  const float* __restrict__ W,   // [16,64]
                                  const float* __restrict__ b,
                                  const float* __restrict__ x_in) {
    int i = blockIdx.x * blockDim.x + threadIdx.x;
    if (i < NN * HD) {
        int n = i >> 6, j = i & 63;
        float a = b[j];
        #pragma unroll
        for (int k = 0; k < 16; k++)
            a += h_in[n * 16 + k] * W[k * 64 + j];
        g_h[i] = a;
    }
    if (i < NN * 3) g_x[i] = x_in[i];
}

__global__ void embed_edge_kernel(const float* __restrict__ ea,
                                  const float* __restrict__ W,   // [8,64]
                                  const float* __restrict__ b) {
    int i = blockIdx.x * blockDim.x + threadIdx.x;
    if (i >= NE * HD) return;
    int e = i >> 6, j = i & 63;
    float a = b[j];
    #pragma unroll
    for (int k = 0; k < 8; k++)
        a += ea[e * 8 + k] * W[k * 64 + j];
    g_e[i] = a;
}

// ---------------------------------------------------------------------------
// Per-layer node projections: g_pa = h @ W1[0:64], g_pb = h @ W1[64:128].
// Also zeroes g_agg / g_dx for this layer.
// ---------------------------------------------------------------------------
#define P_T   512
#define P_TE  64
#define P_HS  68
#define POFF_W 0                      // 64 k x 128 jj = 8192 floats
#define POFF_H 8192                   // 64 x 68
#define PAB_SMEM_FLOATS (POFF_H + P_TE * P_HS)
#define PAB_SMEM_BYTES  (PAB_SMEM_FLOATS * 4)
#define P_TILES ((NN + P_TE - 1) / P_TE)

__global__ void __launch_bounds__(P_T, 2)
pab_kernel(const float* __restrict__ W1) {
    extern __shared__ float sm[];
    float* sW = sm + POFF_W;
    float* sH = sm + POFF_H;
    const int tid = threadIdx.x;

    // zero the per-layer accumulators (grid-stride)
    for (int i = blockIdx.x * P_T + tid; i < NN * HD; i += gridDim.x * P_T)
        g_agg[i] = 0.0f;
    for (int i = blockIdx.x * P_T + tid; i < NN * 3; i += gridDim.x * P_T)
        g_dx[i] = 0.0f;

    for (int idx = tid; idx < 8192; idx += P_T) {
        int k = idx >> 7, jj = idx & 127;
        sW[idx] = (jj < 64) ? W1[k * 64 + jj] : W1[(64 + k) * 64 + (jj - 64)];
    }
    __syncthreads();

    const int jc = tid & 31;
    const int nr = tid >> 5;
    const int j0 = jc * 4;
    const int nb = nr * 4;

    for (int tile = blockIdx.x; tile < P_TILES; tile += gridDim.x) {
        const int n0 = tile * P_TE;
        for (int idx = tid; idx < P_TE * 16; idx += P_T) {
            int nl = idx >> 4, j4 = (idx & 15) * 4;
            int n = n0 + nl;
            float4 hv = make_float4(0.f, 0.f, 0.f, 0.f);
            if (n < NN) hv = *(const float4*)(&g_h[n * 64 + j4]);
            *(float4*)(sH + nl * P_HS + j4) = hv;
        }
        __syncthreads();

        unsigned long long acc[4][2];
        const unsigned long long z = pack2(0.f, 0.f);
        #pragma unroll
        for (int e = 0; e < 4; e++) { acc[e][0] = z; acc[e][1] = z; }
        #pragma unroll 2
        for (int k = 0; k < 64; k += 4) {
            float4 v4[4];
            #pragma unroll
            for (int e = 0; e < 4; e++)
                v4[e] = *(const float4*)(sH + (nb + e) * P_HS + k);
            #pragma unroll
            for (int kk = 0; kk < 4; kk++) {
                ulonglong2 w = *(const ulonglong2*)(sW + (k + kk) * 128 + j0);
                #pragma unroll
                for (int e = 0; e < 4; e++) {
                    float v = ((const float*)&v4[e])[kk];
                    unsigned long long vv = pack2(v, v);
                    ffma2(acc[e][0], vv, w.x);
                    ffma2(acc[e][1], vv, w.y);
                }
            }
        }
        #pragma unroll
        for (int e = 0; e < 4; e++) {
            int n = n0 + nb + e;
            if (n < NN) {
                float a0, a1, a2, a3;
                unpack2(acc[e][0], a0, a1);
                unpack2(acc[e][1], a2, a3);
                float4 o = make_float4(a0, a1, a2, a3);
                if (j0 < 64)
                    *(float4*)(&g_pa[n * 64 + j0]) = o;
                else
                    *(float4*)(&g_pb[n * 64 + (j0 - 64)]) = o;
            }
        }
        __syncthreads();
    }
}

// ---------------------------------------------------------------------------
// Edge kernel (per layer):
//   m1 = silu(b1 + Pa[row] + Pb[col] + rad*wr + e @ W1e)   (k=64)
//   m  = silu(m1 @ W2 + b2) * edge_mask  -> g_e (STG) + g_agg (red) from regs
//   c1 = silu(m @ cW1 + cb1); s = c1 . cW2  -> register dot + shfl reduce
// 256 edges/tile, 512 threads, 1 CTA/SM (16 warps). Warp covers 32 cols x
// 32 edges; thread tile = 4 edges x 8 cols (edges eb0+{0,8,16,24}, conflict-
// free LDS). Next tile's indices/mask/e-features/coords register-prefetched.
// ---------------------------------------------------------------------------
#define E_T    512
#define E_TE   256
#define E_SP   68

#define OFF_W1E  0
#define OFF_W2   (OFF_W1E + 4096)
#define OFF_CW1  (OFF_W2 + 4096)
#define OFF_WR   (OFF_CW1 + 4096)
#define OFF_B1   (OFF_WR + 64)
#define OFF_B2   (OFF_B1 + 64)
#define OFF_CB1  (OFF_B2 + 64)
#define OFF_CW2  (OFF_CB1 + 64)
#define OFF_IN   (OFF_CW2 + 64)
#define OFF_M1   (OFF_IN + E_TE * E_SP)
#define OFF_CD   (OFF_M1 + E_TE * E_SP)
#define OFF_DOT  (OFF_CD + 3 * E_TE)
#define OFF_RAD  (OFF_DOT + 2 * E_TE)
#define OFF_MSK  (OFF_RAD + E_TE)
#define OFF_ROW  (OFF_MSK + E_TE)
#define OFF_COL  (OFF_ROW + E_TE)
#define EDGE_SMEM_FLOATS (OFF_COL + E_TE)
#define EDGE_SMEM_BYTES  (EDGE_SMEM_FLOATS * 4)

__global__ void __launch_bounds__(E_T, 1)
edge_kernel(const int* __restrict__ eidx,
            const float* __restrict__ edge_mask,
            const float* __restrict__ W1, const float* __restrict__ b1,
            const float* __restrict__ W2, const float* __restrict__ b2,
            const float* __restrict__ cw1, const float* __restrict__ cb1,
            const float* __restrict__ cw2) {
    extern __shared__ float sm[];
    float* sW1E = sm + OFF_W1E;
    float* sW2  = sm + OFF_W2;
    float* sCW1 = sm + OFF_CW1;
    float* sWr  = sm + OFF_WR;
    float* sB1  = sm + OFF_B1;
    float* sB2  = sm + OFF_B2;
    float* sCB1 = sm + OFF_CB1;
    float* sCW2 = sm + OFF_CW2;
    float* sIn  = sm + OFF_IN;     // e features, stride 68
    float* sM1  = sm + OFF_M1;
    float* sM   = sm + OFF_IN;     // row-aligned alias of sIn (holds m)
    float* sCD  = sm + OFF_CD;
    float* sDot = sm + OFF_DOT;    // [2][256] half-dot exchange
    float* sRad = sm + OFF_RAD;
    float* sMsk = sm + OFF_MSK;
    int*   sRow = (int*)(sm + OFF_ROW);
    int*   sCol = (int*)(sm + OFF_COL);

    const int tid = threadIdx.x;

    // W1 rows: 0..63=h_row(->Pa), 64..127=h_col(->Pb), 128=radial, 129..192=e
    for (int idx = tid; idx < 4096; idx += E_T) {
        int k = idx >> 6, j = idx & 63;
        sW1E[idx] = W1[(129 + k) * 64 + j];
        sW2[idx]  = W2[idx];
        sCW1[idx] = cw1[idx];
    }
    if (tid < 64) {
        sWr[tid]  = W1[128 * 64 + tid];
        sB1[tid]  = b1[tid];
        sB2[tid]  = b2[tid];
        sCB1[tid] = cb1[tid];
        sCW2[tid] = cw2[tid];
    }
    __syncthreads();

    // warp covers one 32-col half of 32 edges; thread: 4 edges x 8 cols
    const int warp = tid >> 5;
    const int lane = tid & 31;
    const int half = warp & 1;      // col half
    const int q    = warp >> 1;     // edge group of 32 (pair id), 0..7
    const int jc   = lane & 3;      // 4 col groups x 8
    const int erl  = lane >> 2;     // 8 consecutive base rows
    const int j0   = half * 32 + jc * 8;
    const int eb0  = q * 32 + erl;  // edges eb0 + {0,8,16,24}

    const int NT = NE / E_TE;

    // ---- prologue prefetch for first tile ----
    int tile = blockIdx.x;
    int pr = 0, pc = 0;
    float pmsk = 0.f;
    float prx0 = 0.f, prx1 = 0.f, prx2 = 0.f;
    float pcx0 = 0.f, pcx1 = 0.f, pcx2 = 0.f;
    float4 pfe[8];
    if (tile < NT) {
        if (tid < E_TE) {
            int e = tile * E_TE + tid;
            pr = eidx[e]; pc = eidx[NE + e]; pmsk = edge_mask[e];
        }
        #pragma unroll
        for (int s = 0; s < 8; s++) {
            int idx = tid + s * E_T;
            int el = idx >> 4, j4 = (idx & 15) * 4;
            pfe[s] = *(const float4*)(&g_e[(tile * E_TE + el) * 64 + j4]);
        }
        if (tid < E_TE) {
            prx0 = g_x[pr * 3 + 0]; prx1 = g_x[pr * 3 + 1]; prx2 = g_x[pr * 3 + 2];
            pcx0 = g_x[pc * 3 + 0]; pcx1 = g_x[pc * 3 + 1]; pcx2 = g_x[pc * 3 + 2];
        }
    }

    for (; tile < NT; tile += gridDim.x) {
        const int e0 = tile * E_TE;

        // ---- consume prefetched tile state into smem ----
        if (tid < E_TE) {
            sRow[tid] = pr;
            sCol[tid] = pc;
            float dx = prx0 - pcx0;
            float dy = prx1 - pcx1;
            float dz = prx2 - pcx2;
            float rad = dx * dx + dy * dy + dz * dz;
            float inv = 1.0f / (sqrtf(rad) + 1.0f);
            sCD[tid * 3 + 0] = dx * inv;
            sCD[tid * 3 + 1] = dy * inv;
            sCD[tid * 3 + 2] = dz * inv;
            sRad[tid] = rad;
            sMsk[tid] = pmsk;
        }
        #pragma unroll
        for (int s = 0; s < 8; s++) {
            int idx = tid + s * E_T;
            int el = idx >> 4, j4 = (idx & 15) * 4;
            *(float4*)(sIn + el * E_SP + j4) = pfe[s];
        }
        __syncthreads();

        // ---- issue next-tile prefetch (indices, mask, e-features) ----
        const int ntile = tile + gridDim.x;
        const bool hn = ntile < NT;
        if (hn) {
            if (tid < E_TE) {
                int e = ntile * E_TE + tid;
                pr = eidx[e]; pc = eidx[NE + e]; pmsk = edge_mask[e];
            }
            #pragma unroll
            for (int s = 0; s < 8; s++) {
                int idx = tid + s * E_T;
                int el = idx >> 4, j4 = (idx & 15) * 4;
                pfe[s] = *(const float4*)(&g_e[(ntile * E_TE + el) * 64 + j4]);
            }
        }

        // ---- GEMM1: init from Pa/Pb (direct global) + rad, k=64 over e ----
        unsigned long long acc[4][4];
        {
            float4 b1a = *(const float4*)(sB1 + j0);
            float4 b1b = *(const float4*)(sB1 + j0 + 4);
            float4 wra = *(const float4*)(sWr + j0);
            float4 wrb = *(const float4*)(sWr + j0 + 4);
            #pragma unroll
            for (int e = 0; e < 4; e++) {
                int row = eb0 + 8 * e;
                int rn = sRow[row], cn = sCol[row];
                float4 pa0 = *(const float4*)(&g_pa[rn * 64 + j0]);
                float4 pa1 = *(const float4*)(&g_pa[rn * 64 + j0 + 4]);
                float4 pb0 = *(const float4*)(&g_pb[cn * 64 + j0]);
                float4 pb1 = *(const float4*)(&g_pb[cn * 64 + j0 + 4]);
                float rad = sRad[row];
                acc[e][0] = pack2(b1a.x + pa0.x + pb0.x + rad * wra.x,
                                  b1a.y + pa0.y + pb0.y + rad * wra.y);
                acc[e][1] = pack2(b1a.z + pa0.z + pb0.z + rad * wra.z,
                                  b1a.w + pa0.w + pb0.w + rad * wra.w);
                acc[e][2] = pack2(b1b.x + pa1.x + pb1.x + rad * wrb.x,
                                  b1b.y + pa1.y + pb1.y + rad * wrb.y);
                acc[e][3] = pack2(b1b.z + pa1.z + pb1.z + rad * wrb.z,
                                  b1b.w + pa1.w + pb1.w + rad * wrb.w);
            }
        }
        #pragma unroll 2
        for (int k = 0; k < 64; k += 4) {
            float4 v4[4];
            #pragma unroll
            for (int e = 0; e < 4; e++)
                v4[e] = *(const float4*)(sIn + (eb0 + 8 * e) * E_SP + k);
            #pragma unroll
            for (int kk = 0; kk < 4; kk++) {
                ulonglong2 wa = *(const ulonglong2*)(sW1E + (k + kk) * 64 + j0);
                ulonglong2 wb = *(const ulonglong2*)(sW1E + (k + kk) * 64 + j0 + 4);
                #pragma unroll
                for (int e = 0; e < 4; e++) {
                    float v = ((const float*)&v4[e])[kk];
                    unsigned long long vv = pack2(v, v);
                    ffma2(acc[e][0], vv, wa.x);
                    ffma2(acc[e][1], vv, wa.y);
                    ffma2(acc[e][2], vv, wb.x);
                    ffma2(acc[e][3], vv, wb.y);
                }
            }
        }
        #pragma unroll
        for (int e = 0; e < 4; e++) {
            int row = eb0 + 8 * e;
            float a0, a1, a2, a3, a4, a5, a6, a7;
            unpack2(acc[e][0], a0, a1);
            unpack2(acc[e][1], a2, a3);
            unpack2(acc[e][2], a4, a5);
            unpack2(acc[e][3], a6, a7);
            float4 o0, o1;
            o0.x = silu_f(a0); o0.y = silu_f(a1);
            o0.z = silu_f(a2); o0.w = silu_f(a3);
            o1.x = silu_f(a4); o1.y = silu_f(a5);
            o1.z = silu_f(a6); o1.w = silu_f(a7);
            *(float4*)(sM1 + row * E_SP + j0)     = o0;
            *(float4*)(sM1 + row * E_SP + j0 + 4) = o1;
        }
        pair_bar(1 + q);   // pair done with GEMM1 (sIn rows consumed)

        // ---- dependent coord prefetch (pr/pc arrived during GEMM1) ----
        if (hn && tid < E_TE) {
            prx0 = g_x[pr * 3 + 0]; prx1 = g_x[pr * 3 + 1]; prx2 = g_x[pr * 3 + 2];
            pcx0 = g_x[pc * 3 + 0]; pcx1 = g_x[pc * 3 + 1]; pcx2 = g_x[pc * 3 + 2];
        }

        // ---- GEMM2: m = silu(m1 @ W2 + b2) * mask ----
        // m -> sM (own rows, for GEMM3) + g_e STG + g_agg red, all from regs.
        {
            float4 b2a = *(const float4*)(sB2 + j0);
            float4 b2b = *(const float4*)(sB2 + j0 + 4);
            #pragma unroll
            for (int e = 0; e < 4; e++) {
                acc[e][0] = pack2(b2a.x, b2a.y);
                acc[e][1] = pack2(b2a.z, b2a.w);
                acc[e][2] = pack2(b2b.x, b2b.y);
                acc[e][3] = pack2(b2b.z, b2b.w);
            }
        }
        #pragma unroll 2
        for (int k = 0; k < 64; k += 4) {
            float4 v4[4];
            #pragma unroll
            for (int e = 0; e < 4; e++)
                v4[e] = *(const float4*)(sM1 + (eb0 + 8 * e) * E_SP + k);
            #pragma unroll
            for (int kk = 0; kk < 4; kk++) {
                ulonglong2 wa = *(const ulonglong2*)(sW2 + (k + kk) * 64 + j0);
                ulonglong2 wb = *(const ulonglong2*)(sW2 + (k + kk) * 64 + j0 + 4);
                #pragma unroll
                for (int e = 0; e < 4; e++) {
                    float v = ((const float*)&v4[e])[kk];
                    unsigned long long vv = pack2(v, v);
                    ffma2(acc[e][0], vv, wa.x);
                    ffma2(acc[e][1], vv, wa.y);
                    ffma2(acc[e][2], vv, wb.x);
                    ffma2(acc[e][3], vv, wb.y);
                }
            }
        }
        #pragma unroll
        for (int e = 0; e < 4; e++) {
            int row = eb0 + 8 * e;
            float a0, a1, a2, a3, a4, a5, a6, a7;
            unpack2(acc[e][0], a0, a1);
            unpack2(acc[e][1], a2, a3);
            unpack2(acc[e][2], a4, a5);
            unpack2(acc[e][3], a6, a7);
            float mk = sMsk[row];
            float4 o0, o1;
            o0.x = silu_f(a0) * mk; o0.y = silu_f(a1) * mk;
            o0.z = silu_f(a2) * mk; o0.w = silu_f(a3) * mk;
            o1.x = silu_f(a4) * mk; o1.y = silu_f(a5) * mk;
            o1.z = silu_f(a6) * mk; o1.w = silu_f(a7) * mk;
            *(float4*)(sM + row * E_SP + j0)     = o0;
            *(float4*)(sM + row * E_SP + j0 + 4) = o1;
            *(float4*)(&g_e[(e0 + row) * 64 + j0])     = o0;
            *(float4*)(&g_e[(e0 + row) * 64 + j0 + 4]) = o1;
            red_add_v4(&g_agg[sRow[row] * 64 + j0], o0);
            red_add_v4(&g_agg[sRow[row] * 64 + j0 + 4], o1);
        }
        pair_bar(1 + q);   // m complete for this pair's edges

        // ---- GEMM3 (coord hidden) + register dot with cW2 ----
        {
            float4 bca = *(const float4*)(sCB1 + j0);
            float4 bcb = *(const float4*)(sCB1 + j0 + 4);
            #pragma unroll
            for (int e = 0; e < 4; e++) {
                acc[e][0] = pack2(bca.x, bca.y);
                acc[e][1] = pack2(bca.z, bca.w);
                acc[e][2] = pack2(bcb.x, bcb.y);
                acc[e][3] = pack2(bcb.z, bcb.w);
            }
        }
        #pragma unroll 2
        for (int k = 0; k < 64; k += 4) {
            float4 v4[4];
            #pragma unroll
            for (int e = 0; e < 4; e++)
                v4[e] = *(const float4*)(sM + (eb0 + 8 * e) * E_SP + k);
            #pragma unroll
            for (int kk = 0; kk < 4; kk++) {
                ulonglong2 wa = *(const ulonglong2*)(sCW1 + (k + kk) * 64 + j0);
                ulonglong2 wb = *(const ulonglong2*)(sCW1 + (k + kk) * 64 + j0 + 4);
                #pragma unroll
                for (int e = 0; e < 4; e++) {
                    float v = ((const float*)&v4[e])[kk];
                    unsigned long long vv = pack2(v, v);
                    ffma2(acc[e][0], vv, wa.x);
                    ffma2(acc[e][1], vv, wa.y);
                    ffma2(acc[e][2], vv, wb.x);
                    ffma2(acc[e][3], vv, wb.y);
                }
            }
        }
        {
            float4 c2a = *(const float4*)(sCW2 + j0);
            float4 c2b = *(const float4*)(sCW2 + j0 + 4);
            float part[4];
            #pragma unroll
            for (int e = 0; e < 4; e++) {
                float a0, a1, a2, a3, a4, a5, a6, a7;
                unpack2(acc[e][0], a0, a1);
                unpack2(acc[e][1], a2, a3);
                unpack2(acc[e][2], a4, a5);
                unpack2(acc[e][3], a6, a7);
                part[e] = silu_f(a0) * c2a.x + silu_f(a1) * c2a.y
                        + silu_f(a2) * c2a.z + silu_f(a3) * c2a.w
                        + silu_f(a4) * c2b.x + silu_f(a5) * c2b.y
                        + silu_f(a6) * c2b.z + silu_f(a7) * c2b.w;
            }
            // reduce over the 4 jc lanes (lane bits 0..1)
            #pragma unroll
            for (int e = 0; e < 4; e++) {
                part[e] += __shfl_xor_sync(0xffffffffu, part[e], 1);
                part[e] += __shfl_xor_sync(0xffffffffu, part[e], 2);
            }
            if (jc == 0) {
                #pragma unroll
                for (int e = 0; e < 4; e++)
                    sDot[half * E_TE + eb0 + 8 * e] = part[e];
            }
        }
        pair_bar(1 + q);   // both halves' partial dots visible
        if (half == 0 && jc == 0) {
            #pragma unroll
            for (int e = 0; e < 4; e++) {
                int row = eb0 + 8 * e;
                float s = sDot[row] + sDot[E_TE + row];
                int r = sRow[row];
                red_add_f(&g_dx[r * 3 + 0], sCD[row * 3 + 0] * s);
                red_add_f(&g_dx[r * 3 + 1], sCD[row * 3 + 1] * s);
                red_add_f(&g_dx[r * 3 + 2], sCD[row * 3 + 2] * s);
            }
        }
        __syncthreads();   // protect sIn/sM/scalars before next staging
    }
}

// ---------------------------------------------------------------------------
// Node kernel: h = (h + MLP([h|agg])) * mask ; x = (x + dx) * mask
// ---------------------------------------------------------------------------
#define N_TE 64
#define N_NS 132
#define N_SP 68
#define NOFF_W1  0
#define NOFF_B1  (NOFF_W1 + 128 * 64)
#define NOFF_W2  (NOFF_B1 + 64)
#define NOFF_B2  (NOFF_W2 + 4096)
#define NOFF_IN  (NOFF_B2 + 64)
#define NOFF_M1  (NOFF_IN + N_TE * N_NS)
#define NOFF_MK  (NOFF_M1 + N_TE * N_SP)
#define NODE_SMEM_FLOATS (NOFF_MK + N_TE)
#define NODE_SMEM_BYTES  (NODE_SMEM_FLOATS * 4)
#define N_TILES ((NN + N_TE - 1) / N_TE)

__global__ void __launch_bounds__(256, 2)
node_kernel(const float* __restrict__ W1, const float* __restrict__ b1,
            const float* __restrict__ W2, const float* __restrict__ b2,
            const float* __restrict__ node_mask) {
    extern __shared__ float sm[];
    float* sW1 = sm + NOFF_W1;
    float* sB1 = sm + NOFF_B1;
    float* sW2 = sm + NOFF_W2;
    float* sB2 = sm + NOFF_B2;
    float* sIn = sm + NOFF_IN;
    float* sM1 = sm + NOFF_M1;
    float* sMk = sm + NOFF_MK;

    const int tid = threadIdx.x;
    for (int idx = tid; idx < 128 * 64; idx += 256) sW1[idx] = W1[idx];
    for (int idx = tid; idx < 4096; idx += 256)     sW2[idx] = W2[idx];
    if (tid < 64) { sB1[tid] = b1[tid]; sB2[tid] = b2[tid]; }
    __syncthreads();

    const int jc = tid & 15;
    const int nr = tid >> 4;
    const int j0 = jc * 4;
    const int nb = nr * 4;

    const unsigned long long b1p0 = pack2(sB1[j0], sB1[j0 + 1]);
    const unsigned long long b1p1 = pack2(sB1[j0 + 2], sB1[j0 + 3]);
    const unsigned long long b2p0 = pack2(sB2[j0], sB2[j0 + 1]);
    const unsigned long long b2p1 = pack2(sB2[j0 + 2], sB2[j0 + 3]);

    for (int tile = blockIdx.x; tile < N_TILES; tile += gridDim.x) {
        const int n0 = tile * N_TE;
        const bool full = (n0 + N_TE <= NN);

        if (full) {
            for (int idx = tid; idx < N_TE * 16; idx += 256) {
                int nl = idx >> 4, j4 = (idx & 15) * 4;
                int n = n0 + nl;
                float4 hv = *(const float4*)(&g_h[n * 64 + j4]);
                float4 av = *(const float4*)(&g_agg[n * 64 + j4]);
                *(float4*)(sIn + nl * N_NS + j4)      = hv;
                *(float4*)(sIn + nl * N_NS + 64 + j4) = av;
            }
        } else {
            for (int idx = tid; idx < N_TE * 64; idx += 256) {
                int nl = idx >> 6, j = idx & 63;
                int n = n0 + nl;
                float hv = 0.0f, av = 0.0f;
                if (n < NN) { hv = g_h[n * 64 + j]; av = g_agg[n * 64 + j]; }
                sIn[nl * N_NS + j]      = hv;
                sIn[nl * N_NS + 64 + j] = av;
            }
        }
        if (tid < N_TE) {
            int n = n0 + tid;
            sMk[tid] = (n < NN) ? node_mask[n] : 0.0f;
        }
        __syncthreads();

        unsigned long long acc[4][2];
        #pragma unroll
        for (int e = 0; e < 4; e++) { acc[e][0] = b1p0; acc[e][1] = b1p1; }
        #pragma unroll 2
        for (int k = 0; k < 128; k += 4) {
            float4 v4[4];
            #pragma unroll
            for (int e = 0; e < 4; e++)
                v4[e] = *(const float4*)(sIn + (nb + e) * N_NS + k);
            #pragma unroll
            for (int kk = 0; kk < 4; kk++) {
                ulonglong2 w = *(const ulonglong2*)(sW1 + (k + kk) * 64 + j0);
                #pragma unroll
                for (int e = 0; e < 4; e++) {
                    float v = ((const float*)&v4[e])[kk];
                    unsigned long long vv = pack2(v, v);
                    ffma2(acc[e][0], vv, w.x);
                    ffma2(acc[e][1], vv, w.y);
                }
            }
        }
        #pragma unroll
        for (int e = 0; e < 4; e++) {
            float a0, a1, a2, a3;
            unpack2(acc[e][0], a0, a1);
            unpack2(acc[e][1], a2, a3);
            float4 o;
            o.x = silu_f(a0); o.y = silu_f(a1);
            o.z = silu_f(a2); o.w = silu_f(a3);
            *(float4*)(sM1 + (nb + e) * N_SP + j0) = o;
        }
        __syncthreads();

        #pragma unroll
        for (int e = 0; e < 4; e++) { acc[e][0] = b2p0; acc[e][1] = b2p1; }
        #pragma unroll 2
        for (int k = 0; k < 64; k += 4) {
            float4 v4[4];
            #pragma unroll
            for (int e = 0; e < 4; e++)
                v4[e] = *(const float4*)(sM1 + (nb + e) * N_SP + k);
            #pragma unroll
            for (int kk = 0; kk < 4; kk++) {
                ulonglong2 w = *(const ulonglong2*)(sW2 + (k + kk) * 64 + j0);
                #pragma unroll
                for (int e = 0; e < 4; e++) {
                    float v = ((const float*)&v4[e])[kk];
                    unsigned long long vv = pack2(v, v);
                    ffma2(acc[e][0], vv, w.x);
                    ffma2(acc[e][1], vv, w.y);
                }
            }
        }
        #pragma unroll
        for (int e = 0; e < 4; e++) {
            int n = n0 + nb + e;
            if (n < NN) {
                float a0, a1, a2, a3;
                unpack2(acc[e][0], a0, a1);
                unpack2(acc[e][1], a2, a3);
                float mk = sMk[nb + e];
                float4 o;
                o.x = (sIn[(nb + e) * N_NS + j0 + 0] + a0) * mk;
                o.y = (sIn[(nb + e) * N_NS + j0 + 1] + a1) * mk;
                o.z = (sIn[(nb + e) * N_NS + j0 + 2] + a2) * mk;
                o.w = (sIn[(nb + e) * N_NS + j0 + 3] + a3) * mk;
                *(float4*)(&g_h[n * 64 + j0]) = o;
            }
        }
        // x update
        if (tid < N_TE * 3) {
            int n = n0 + tid / 3;
            int k = tid % 3;
            if (n < NN) {
                float mk = node_mask[n];
                g_x[n * 3 + k] = (g_x[n * 3 + k] + g_dx[n * 3 + k]) * mk;
            }
        }
        __syncthreads();
    }
}

// ---------------------------------------------------------------------------
// Output kernels
// ---------------------------------------------------------------------------
__global__ void out_h_x_kernel(const float* __restrict__ W,  // [64,16]
                               const float* __restrict__ b,
                               const float* __restrict__ node_mask,
                               float* __restrict__ out) {
    int i = blockIdx.x * blockDim.x + threadIdx.x;
    if (i < NN * 16) {
        int n = i >> 4, j = i & 15;
        float a = b[j];
        #pragma unroll 4
        for (int k4 = 0; k4 < 64; k4 += 4) {
            float4 h4 = *(const float4*)(&g_h[n * 64 + k4]);
            a += h4.x * W[(k4 + 0) * 16 + j];
            a += h4.y * W[(k4 + 1) * 16 + j];
            a += h4.z * W[(k4 + 2) * 16 + j];
            a += h4.w * W[(k4 + 3) * 16 + j];
        }
        out[i] = a * node_mask[n];
    }
    if (i < NN * 3) out[NN * 16 + i] = g_x[i];
}

__global__ void out_e_kernel(const float* __restrict__ W,  // [64,8]
                             const float* __restrict__ b,
                             const float* __restrict__ edge_mask,
                             float* __restrict__ out) {
    int i = blockIdx.x * blockDim.x + threadIdx.x;
    if (i >= NE * 8) return;
    int e = i >> 3, j = i & 7;
    float a = b[j];
    #pragma unroll 4
    for (int k4 = 0; k4 < 64; k4 += 4) {
        float4 e4 = *(const float4*)(&g_e[e * 64 + k4]);
        a += e4.x * W[(k4 + 0) * 8 + j];
        a += e4.y * W[(k4 + 1) * 8 + j];
        a += e4.z * W[(k4 + 2) * 8 + j];
        a += e4.w * W[(k4 + 3) * 8 + j];
    }
    out[i] = a * edge_mask[e];
}

// ---------------------------------------------------------------------------
// Launch
// ---------------------------------------------------------------------------
extern "C" void kernel_launch(void* const* d_in, const int* in_sizes, int n_in,
                              void* d_out, int out_size) {
    const float* h_in      = (const float*)d_in[0];
    const float* x_in      = (const float*)d_in[1];
    const float* edge_attr = (const float*)d_in[2];
    const float* node_mask = (const float*)d_in[3];
    const float* edge_mask = (const float*)d_in[4];
    const float* Wn_in     = (const float*)d_in[5];
    const float* bn_in     = (const float*)d_in[6];
    const float* Wn_out    = (const float*)d_in[7];
    const float* bn_out    = (const float*)d_in[8];
    const float* We_in     = (const float*)d_in[9];
    const float* be_in     = (const float*)d_in[10];
    const float* We_out    = (const float*)d_in[11];
    const float* be_out    = (const float*)d_in[12];
    const float* eW1       = (const float*)d_in[13];
    const float* eb1       = (const float*)d_in[14];
    const float* eW2       = (const float*)d_in[15];
    const float* eb2       = (const float*)d_in[16];
    const float* nW1       = (const float*)d_in[17];
    const float* nb1       = (const float*)d_in[18];
    const float* nW2       = (const float*)d_in[19];
    const float* nb2       = (const float*)d_in[20];
    const float* cW1       = (const float*)d_in[21];
    const float* cb1       = (const float*)d_in[22];
    const float* cW2       = (const float*)d_in[23];
    const int*   edge_index = (const int*)d_in[24];
    float* out = (float*)d_out;

    cudaFuncSetAttribute(edge_kernel, cudaFuncAttributeMaxDynamicSharedMemorySize,
                         EDGE_SMEM_BYTES);
    cudaFuncSetAttribute(node_kernel, cudaFuncAttributeMaxDynamicSharedMemorySize,
                         NODE_SMEM_BYTES);
    cudaFuncSetAttribute(pab_kernel, cudaFuncAttributeMaxDynamicSharedMemorySize,
                         PAB_SMEM_BYTES);

    embed_node_kernel<<<(NN * HD + 255) / 256, 256>>>(h_in, Wn_in, bn_in, x_in);
    embed_edge_kernel<<<(NE * HD + 255) / 256, 256>>>(edge_attr, We_in, be_in);

    for (int l = 0; l < NL; l++) {
        pab_kernel<<<304, P_T, PAB_SMEM_BYTES>>>(eW1 + l * 193 * 64);
        edge_kernel<<<152, E_T, EDGE_SMEM_BYTES>>>(
            edge_index, edge_mask,
            eW1 + l * 193 * 64, eb1 + l * 64,
            eW2 + l * 4096,     eb2 + l * 64,
            cW1 + l * 4096,     cb1 + l * 64,
            cW2 + l * 64);
        node_kernel<<<304, 256, NODE_SMEM_BYTES>>>(
            nW1 + l * 128 * 64, nb1 + l * 64,
            nW2 + l * 4096,     nb2 + l * 64,
            node_mask);
    }

    out_h_x_kernel<<<(NN * 16 + 255) / 256, 256>>>(Wn_out, bn_out, node_mask, out);
    out_e_kernel<<<(NE * 8 + 255) / 256, 256>>>(We_out, be_out, edge_mask,
                                                out + NN * 16 + NN * 3);
}

// round 16
// speedup vs baseline: 1.0328x; 1.0328x over previous
#include <cuda_runtime.h>
#include <math.h>

#define NN 50000
#define NE 800000
#define HD 64
#define NL 4

// Persistent state between launches (device globals: allocation-free).
__device__ float g_h[NN * HD];     // current node embedding
__device__ float g_e[NE * HD];     // current edge feature / message
__device__ float g_x[NN * 3];      // current coordinates
__device__ float g_agg[NN * HD];   // per-layer message aggregation
__device__ float g_dx[NN * 3];     // per-layer coordinate delta
__device__ float g_pa[NN * HD];    // h @ W1[0:64]   (row-half projection)
__device__ float g_pb[NN * HD];    // h @ W1[64:128] (col-half projection)

__device__ __forceinline__ float silu_f(float v) {
    return v / (1.0f + __expf(-v));
}

// ---- packed f32x2 helpers (Blackwell dual-rate fp32 path) ----
__device__ __forceinline__ unsigned long long pack2(float lo, float hi) {
    unsigned long long r;
    asm("mov.b64 %0, {%1, %2};" : "=l"(r) : "f"(lo), "f"(hi));
    return r;
}
__device__ __forceinline__ void unpack2(unsigned long long v, float& lo, float& hi) {
    asm("mov.b64 {%0, %1}, %2;" : "=f"(lo), "=f"(hi) : "l"(v));
}
__device__ __forceinline__ void ffma2(unsigned long long& d,
                                      unsigned long long a,
                                      unsigned long long b) {
    asm("fma.rn.f32x2 %0, %1, %2, %0;" : "+l"(d) : "l"(a), "l"(b));
}
__device__ __forceinline__ void red_add_v4(float* p, float4 v) {
    asm volatile("red.global.add.v4.f32 [%0], {%1, %2, %3, %4};"
                 :: "l"(p), "f"(v.x), "f"(v.y), "f"(v.z), "f"(v.w) : "memory");
}
__device__ __forceinline__ void red_add_f(float* p, float v) {
    asm volatile("red.global.add.f32 [%0], %1;" :: "l"(p), "f"(v) : "memory");
}
__device__ __forceinline__ void pair_bar(int id) {
    asm volatile("bar.sync %0, 64;" :: "r"(id) : "memory");
}

// ---------------------------------------------------------------------------
// Embedding kernel (node only; edge embed fused into first edge layer)
// ---------------------------------------------------------------------------
__global__ void embed_node_kernel(const float* __restrict__ h_in,
                                  const float* __restrict__ W,   // [16,64]
                                  const float* __restrict__ b,
                                  const float* __restrict__ x_in) {
    int i = blockIdx.x * blockDim.x + threadIdx.x;
    if (i < NN * HD) {
        int n = i >> 6, j = i & 63;
        float a = b[j];
        #pragma unroll
        for (int k = 0; k < 16; k++)
            a += h_in[n * 16 + k] * W[k * 64 + j];
        g_h[i] = a;
    }
    if (i < NN * 3) g_x[i] = x_in[i];
}

// ---------------------------------------------------------------------------
// Per-layer node projections: g_pa = h @ W1[0:64], g_pb = h @ W1[64:128].
// Also zeroes g_agg / g_dx for this layer.
// ---------------------------------------------------------------------------
#define P_T   512
#define P_TE  64
#define P_HS  68
#define POFF_W 0                      // 64 k x 128 jj = 8192 floats
#define POFF_H 8192                   // 64 x 68
#define PAB_SMEM_FLOATS (POFF_H + P_TE * P_HS)
#define PAB_SMEM_BYTES  (PAB_SMEM_FLOATS * 4)
#define P_TILES ((NN + P_TE - 1) / P_TE)

__global__ void __launch_bounds__(P_T, 2)
pab_kernel(const float* __restrict__ W1) {
    extern __shared__ float sm[];
    float* sW = sm + POFF_W;
    float* sH = sm + POFF_H;
    const int tid = threadIdx.x;

    // zero the per-layer accumulators (grid-stride)
    for (int i = blockIdx.x * P_T + tid; i < NN * HD; i += gridDim.x * P_T)
        g_agg[i] = 0.0f;
    for (int i = blockIdx.x * P_T + tid; i < NN * 3; i += gridDim.x * P_T)
        g_dx[i] = 0.0f;

    for (int idx = tid; idx < 8192; idx += P_T) {
        int k = idx >> 7, jj = idx & 127;
        sW[idx] = (jj < 64) ? W1[k * 64 + jj] : W1[(64 + k) * 64 + (jj - 64)];
    }
    __syncthreads();

    const int jc = tid & 31;
    const int nr = tid >> 5;
    const int j0 = jc * 4;
    const int nb = nr * 4;

    for (int tile = blockIdx.x; tile < P_TILES; tile += gridDim.x) {
        const int n0 = tile * P_TE;
        for (int idx = tid; idx < P_TE * 16; idx += P_T) {
            int nl = idx >> 4, j4 = (idx & 15) * 4;
            int n = n0 + nl;
            float4 hv = make_float4(0.f, 0.f, 0.f, 0.f);
            if (n < NN) hv = *(const float4*)(&g_h[n * 64 + j4]);
            *(float4*)(sH + nl * P_HS + j4) = hv;
        }
        __syncthreads();

        unsigned long long acc[4][2];
        const unsigned long long z = pack2(0.f, 0.f);
        #pragma unroll
        for (int e = 0; e < 4; e++) { acc[e][0] = z; acc[e][1] = z; }
        #pragma unroll 2
        for (int k = 0; k < 64; k += 4) {
            float4 v4[4];
            #pragma unroll
            for (int e = 0; e < 4; e++)
                v4[e] = *(const float4*)(sH + (nb + e) * P_HS + k);
            #pragma unroll
            for (int kk = 0; kk < 4; kk++) {
                ulonglong2 w = *(const ulonglong2*)(sW + (k + kk) * 128 + j0);
                #pragma unroll
                for (int e = 0; e < 4; e++) {
                    float v = ((const float*)&v4[e])[kk];
                    unsigned long long vv = pack2(v, v);
                    ffma2(acc[e][0], vv, w.x);
                    ffma2(acc[e][1], vv, w.y);
                }
            }
        }
        #pragma unroll
        for (int e = 0; e < 4; e++) {
            int n = n0 + nb + e;
            if (n < NN) {
                float a0, a1, a2, a3;
                unpack2(acc[e][0], a0, a1);
                unpack2(acc[e][1], a2, a3);
                float4 o = make_float4(a0, a1, a2, a3);
                if (j0 < 64)
                    *(float4*)(&g_pa[n * 64 + j0]) = o;
                else
                    *(float4*)(&g_pb[n * 64 + (j0 - 64)]) = o;
            }
        }
        __syncthreads();
    }
}

// ---------------------------------------------------------------------------
// Edge kernel (per layer), templated:
//   FIRST: e features computed in-staging from edge_attr @ We_in + be_in
//   LAST:  e_out = (m @ We_out + be_out) * mask written to out; g_e skipped
// Core (all layers):
//   m1 = silu(b1 + Pa[row] + Pb[col] + rad*wr + e @ W1e)   (k=64)
//   m  = silu(m1 @ W2 + b2) * edge_mask  -> g_e STG + g_agg red from regs
//   c1 = silu(m @ cW1 + cb1); s = c1 . cW2  -> register dot + shfl reduce
// 64 edges/tile, 256 threads, 2 CTAs/SM.
// ---------------------------------------------------------------------------
#define E_T    256
#define E_TE   64
#define E_SP   68

#define OFF_W1E  0
#define OFF_WR   (OFF_W1E + 4096)
#define OFF_B1   (OFF_WR + 64)
#define OFF_W2   (OFF_B1 + 64)
#define OFF_B2   (OFF_W2 + 4096)
#define OFF_CW1  (OFF_B2 + 64)
#define OFF_CB1  (OFF_CW1 + 4096)
#define OFF_CW2  (OFF_CB1 + 64)
#define OFF_WE   (OFF_CW2 + 64)      // 512: We_in (8x64) or We_out (64x8)
#define OFF_BE   (OFF_WE + 512)      // 64: be_in or be_out(8)
#define OFF_IN   (OFF_BE + 64)
#define OFF_M1   (OFF_IN + E_TE * E_SP)
#define OFF_CD   (OFF_M1 + E_TE * E_SP)
#define OFF_DOT  (OFF_CD + 3 * E_TE)
#define OFF_RAD  (OFF_DOT + 2 * E_TE)
#define OFF_MSK  (OFF_RAD + E_TE)
#define OFF_ROW  (OFF_MSK + E_TE)
#define OFF_COL  (OFF_ROW + E_TE)
#define EDGE_SMEM_FLOATS (OFF_COL + E_TE)
#define EDGE_SMEM_BYTES  (EDGE_SMEM_FLOATS * 4)

template <int FIRST, int LAST>
__global__ void __launch_bounds__(E_T, 2)
edge_kernel(const int* __restrict__ eidx,
            const float* __restrict__ edge_mask,
            const float* __restrict__ W1, const float* __restrict__ b1,
            const float* __restrict__ W2, const float* __restrict__ b2,
            const float* __restrict__ cw1, const float* __restrict__ cb1,
            const float* __restrict__ cw2,
            const float* __restrict__ ea,      // FIRST: edge_attr [E,8]
            const float* __restrict__ WeX,     // FIRST: We_in ; LAST: We_out
            const float* __restrict__ beX,     // FIRST: be_in ; LAST: be_out
            float* __restrict__ oute) {        // LAST: output e region [E,8]
    extern __shared__ float sm[];
    float* sW1E = sm + OFF_W1E;
    float* sWr  = sm + OFF_WR;
    float* sB1  = sm + OFF_B1;
    float* sW2  = sm + OFF_W2;
    float* sB2  = sm + OFF_B2;
    float* sCW1 = sm + OFF_CW1;
    float* sCB1 = sm + OFF_CB1;
    float* sCW2 = sm + OFF_CW2;
    float* sWE  = sm + OFF_WE;
    float* sBE  = sm + OFF_BE;
    float* sIn  = sm + OFF_IN;     // e features, stride 68
    float* sM1  = sm + OFF_M1;
    float* sM   = sm + OFF_IN;     // row-aligned alias of sIn (holds m)
    float* sCD  = sm + OFF_CD;
    float* sDot = sm + OFF_DOT;    // [2][64] half-dot exchange
    float* sRad = sm + OFF_RAD;
    float* sMsk = sm + OFF_MSK;
    int*   sRow = (int*)(sm + OFF_ROW);
    int*   sCol = (int*)(sm + OFF_COL);

    const int tid = threadIdx.x;

    // W1 rows: 0..63=h_row(->Pa), 64..127=h_col(->Pb), 128=radial, 129..192=e
    for (int idx = tid; idx < 4096; idx += E_T) {
        int k = idx >> 6, j = idx & 63;
        sW1E[idx] = W1[(129 + k) * 64 + j];
        sW2[idx]  = W2[idx];
        sCW1[idx] = cw1[idx];
    }
    if (tid < 64) {
        sWr[tid]  = W1[128 * 64 + tid];
        sB1[tid]  = b1[tid];
        sB2[tid]  = b2[tid];
        sCB1[tid] = cb1[tid];
        sCW2[tid] = cw2[tid];
    }
    if (FIRST || LAST) {
        for (int idx = tid; idx < 512; idx += E_T) sWE[idx] = WeX[idx];
        if (tid < 64) sBE[tid] = (FIRST || tid < 8) ? beX[FIRST ? tid : tid] : 0.f;
    }
    __syncthreads();

    // warp covers one 32-col half of 16 edges; thread tile edges eb0 + 4*e
    const int warp = tid >> 5;
    const int lane = tid & 31;
    const int half = warp & 1;      // col half
    const int q    = warp >> 1;     // edge quarter (pair id)
    const int jc   = lane & 7;      // 8 col groups x 4
    const int erl  = lane >> 3;     // 4 consecutive base rows
    const int j0   = half * 32 + jc * 4;
    const int eb0  = q * 16 + erl;

    const float4 b1f  = *(const float4*)(sB1 + j0);
    const float4 wrf  = *(const float4*)(sWr + j0);
    const float4 cw2f = *(const float4*)(sCW2 + j0);
    const unsigned long long b2p0 = pack2(sB2[j0], sB2[j0 + 1]);
    const unsigned long long b2p1 = pack2(sB2[j0 + 2], sB2[j0 + 3]);
    const unsigned long long bcp0 = pack2(sCB1[j0], sCB1[j0 + 1]);
    const unsigned long long bcp1 = pack2(sCB1[j0 + 2], sCB1[j0 + 3]);

    const int NT = NE / E_TE;

    // ---- prologue prefetch for first tile ----
    int tile = blockIdx.x;
    int pr = 0, pc = 0;
    float pmsk = 0.f;
    float prx0 = 0.f, prx1 = 0.f, prx2 = 0.f;
    float pcx0 = 0.f, pcx1 = 0.f, pcx2 = 0.f;
    float4 pfe[4];
    if (tile < NT) {
        if (tid < E_TE) {
            int e = tile * E_TE + tid;
            pr = eidx[e]; pc = eidx[NE + e]; pmsk = edge_mask[e];
        }
        if (!FIRST) {
            #pragma unroll
            for (int s = 0; s < 4; s++) {
                int idx = tid + s * E_T;
                int el = idx >> 4, j4 = (idx & 15) * 4;
                pfe[s] = *(const float4*)(&g_e[(tile * E_TE + el) * 64 + j4]);
            }
        }
        if (tid < E_TE) {
            prx0 = g_x[pr * 3 + 0]; prx1 = g_x[pr * 3 + 1]; prx2 = g_x[pr * 3 + 2];
            pcx0 = g_x[pc * 3 + 0]; pcx1 = g_x[pc * 3 + 1]; pcx2 = g_x[pc * 3 + 2];
        }
    }

    for (; tile < NT; tile += gridDim.x) {
        const int e0 = tile * E_TE;

        // ---- consume prefetched tile state into smem ----
        if (tid < E_TE) {
            sRow[tid] = pr;
            sCol[tid] = pc;
            float dx = prx0 - pcx0;
            float dy = prx1 - pcx1;
            float dz = prx2 - pcx2;
            float rad = dx * dx + dy * dy + dz * dz;
            float inv = 1.0f / (sqrtf(rad) + 1.0f);
            sCD[tid * 3 + 0] = dx * inv;
            sCD[tid * 3 + 1] = dy * inv;
            sCD[tid * 3 + 2] = dz * inv;
            sRad[tid] = rad;
            sMsk[tid] = pmsk;
        }
        if (FIRST) {
            // e features computed from edge_attr on the fly (k=8 mini-GEMM)
            for (int idx = tid; idx < E_TE * 16; idx += E_T) {
                int el = idx >> 4, j4 = (idx & 15) * 4;
                const float* ear = ea + (size_t)(e0 + el) * 8;
                float4 a = *(const float4*)(sBE + j4);
                #pragma unroll
                for (int k = 0; k < 8; k++) {
                    float v = __ldg(ear + k);
                    float4 w = *(const float4*)(sWE + k * 64 + j4);
                    a.x += v * w.x; a.y += v * w.y;
                    a.z += v * w.z; a.w += v * w.w;
                }
                *(float4*)(sIn + el * E_SP + j4) = a;
            }
        } else {
            #pragma unroll
            for (int s = 0; s < 4; s++) {
                int idx = tid + s * E_T;
                int el = idx >> 4, j4 = (idx & 15) * 4;
                *(float4*)(sIn + el * E_SP + j4) = pfe[s];
            }
        }
        __syncthreads();

        // ---- issue next-tile prefetch (indices, mask, e-features) ----
        const int ntile = tile + gridDim.x;
        const bool hn = ntile < NT;
        if (hn) {
            if (tid < E_TE) {
                int e = ntile * E_TE + tid;
                pr = eidx[e]; pc = eidx[NE + e]; pmsk = edge_mask[e];
            }
            if (!FIRST) {
                #pragma unroll
                for (int s = 0; s < 4; s++) {
                    int idx = tid + s * E_T;
                    int el = idx >> 4, j4 = (idx & 15) * 4;
                    pfe[s] = *(const float4*)(&g_e[(ntile * E_TE + el) * 64 + j4]);
                }
            }
        }

        // ---- GEMM1: init from Pa/Pb (direct global) + rad, k=64 over e ----
        unsigned long long acc[4][2];
        #pragma unroll
        for (int e = 0; e < 4; e++) {
            int row = eb0 + 4 * e;
            float4 pa = *(const float4*)(&g_pa[sRow[row] * 64 + j0]);
            float4 pb = *(const float4*)(&g_pb[sCol[row] * 64 + j0]);
            float rad = sRad[row];
            float f0 = b1f.x + pa.x + pb.x + rad * wrf.x;
            float f1 = b1f.y + pa.y + pb.y + rad * wrf.y;
            float f2 = b1f.z + pa.z + pb.z + rad * wrf.z;
            float f3 = b1f.w + pa.w + pb.w + rad * wrf.w;
            acc[e][0] = pack2(f0, f1);
            acc[e][1] = pack2(f2, f3);
        }
        #pragma unroll 2
        for (int k = 0; k < 64; k += 4) {
            float4 v4[4];
            #pragma unroll
            for (int e = 0; e < 4; e++)
                v4[e] = *(const float4*)(sIn + (eb0 + 4 * e) * E_SP + k);
            #pragma unroll
            for (int kk = 0; kk < 4; kk++) {
                ulonglong2 w = *(const ulonglong2*)(sW1E + (k + kk) * 64 + j0);
                #pragma unroll
                for (int e = 0; e < 4; e++) {
                    float v = ((const float*)&v4[e])[kk];
                    unsigned long long vv = pack2(v, v);
                    ffma2(acc[e][0], vv, w.x);
                    ffma2(acc[e][1], vv, w.y);
                }
            }
        }
        #pragma unroll
        for (int e = 0; e < 4; e++) {
            float a0, a1, a2, a3;
            unpack2(acc[e][0], a0, a1);
            unpack2(acc[e][1], a2, a3);
            float4 o;
            o.x = silu_f(a0); o.y = silu_f(a1);
            o.z = silu_f(a2); o.w = silu_f(a3);
            *(float4*)(sM1 + (eb0 + 4 * e) * E_SP + j0) = o;
        }
        pair_bar(1 + q);   // pair done with GEMM1 (sIn rows consumed)

        // ---- dependent coord prefetch (pr/pc arrived during GEMM1) ----
        if (hn && tid < E_TE) {
            prx0 = g_x[pr * 3 + 0]; prx1 = g_x[pr * 3 + 1]; prx2 = g_x[pr * 3 + 2];
            pcx0 = g_x[pc * 3 + 0]; pcx1 = g_x[pc * 3 + 1]; pcx2 = g_x[pc * 3 + 2];
        }

        // ---- GEMM2: m = silu(m1 @ W2 + b2) * mask ----
        #pragma unroll
        for (int e = 0; e < 4; e++) { acc[e][0] = b2p0; acc[e][1] = b2p1; }
        #pragma unroll 2
        for (int k = 0; k < 64; k += 4) {
            float4 v4[4];
            #pragma unroll
            for (int e = 0; e < 4; e++)
                v4[e] = *(const float4*)(sM1 + (eb0 + 4 * e) * E_SP + k);
            #pragma unroll
            for (int kk = 0; kk < 4; kk++) {
                ulonglong2 w = *(const ulonglong2*)(sW2 + (k + kk) * 64 + j0);
                #pragma unroll
                for (int e = 0; e < 4; e++) {
                    float v = ((const float*)&v4[e])[kk];
                    unsigned long long vv = pack2(v, v);
                    ffma2(acc[e][0], vv, w.x);
                    ffma2(acc[e][1], vv, w.y);
                }
            }
        }
        #pragma unroll
        for (int e = 0; e < 4; e++) {
            int row = eb0 + 4 * e;
            float a0, a1, a2, a3;
            unpack2(acc[e][0], a0, a1);
            unpack2(acc[e][1], a2, a3);
            float mk = sMsk[row];
            float4 o;
            o.x = silu_f(a0) * mk; o.y = silu_f(a1) * mk;
            o.z = silu_f(a2) * mk; o.w = silu_f(a3) * mk;
            *(float4*)(sM + row * E_SP + j0) = o;
            if (!LAST)
                *(float4*)(&g_e[(e0 + row) * 64 + j0]) = o;
            red_add_v4(&g_agg[sRow[row] * 64 + j0], o);
        }
        pair_bar(1 + q);   // m complete for this pair's edges

        if (LAST) {
            // all pairs' m needed for the e_out tile below
            __syncthreads();
            #pragma unroll
            for (int t = 0; t < 2; t++) {
                int idx = tid * 2 + t;          // 0..511
                int el = idx >> 3, p = idx & 7;
                float a = 0.f;
                #pragma unroll 4
                for (int k4 = 0; k4 < 64; k4 += 4) {
                    float4 mv = *(const float4*)(sM + el * E_SP + k4);
                    a += mv.x * sWE[(k4 + 0) * 8 + p];
                    a += mv.y * sWE[(k4 + 1) * 8 + p];
                    a += mv.z * sWE[(k4 + 2) * 8 + p];
                    a += mv.w * sWE[(k4 + 3) * 8 + p];
                }
                oute[(size_t)(e0 + el) * 8 + p] = (a + sBE[p]) * sMsk[el];
            }
        }

        // ---- GEMM3 (coord hidden) + register dot with cW2 ----
        #pragma unroll
        for (int e = 0; e < 4; e++) { acc[e][0] = bcp0; acc[e][1] = bcp1; }
        #pragma unroll 2
        for (int k = 0; k < 64; k += 4) {
            float4 v4[4];
            #pragma unroll
            for (int e = 0; e < 4; e++)
                v4[e] = *(const float4*)(sM + (eb0 + 4 * e) * E_SP + k);
            #pragma unroll
            for (int kk = 0; kk < 4; kk++) {
                ulonglong2 w = *(const ulonglong2*)(sCW1 + (k + kk) * 64 + j0);
                #pragma unroll
                for (int e = 0; e < 4; e++) {
                    float v = ((const float*)&v4[e])[kk];
                    unsigned long long vv = pack2(v, v);
                    ffma2(acc[e][0], vv, w.x);
                    ffma2(acc[e][1], vv, w.y);
                }
            }
        }
        float part[4];
        #pragma unroll
        for (int e = 0; e < 4; e++) {
            float a0, a1, a2, a3;
            unpack2(acc[e][0], a0, a1);
            unpack2(acc[e][1], a2, a3);
            part[e] = silu_f(a0) * cw2f.x + silu_f(a1) * cw2f.y
                    + silu_f(a2) * cw2f.z + silu_f(a3) * cw2f.w;
        }
        // reduce over the 8 jc lanes (lane bits 0..2)
        #pragma unroll
        for (int e = 0; e < 4; e++) {
            part[e] += __shfl_xor_sync(0xffffffffu, part[e], 1);
            part[e] += __shfl_xor_sync(0xffffffffu, part[e], 2);
            part[e] += __shfl_xor_sync(0xffffffffu, part[e], 4);
        }
        if (jc == 0) {
            #pragma unroll
            for (int e = 0; e < 4; e++)
                sDot[half * E_TE + eb0 + 4 * e] = part[e];
        }
        pair_bar(1 + q);   // both halves' partial dots visible
        if (half == 0 && jc == 0) {
            #pragma unroll
            for (int e = 0; e < 4; e++) {
                int row = eb0 + 4 * e;
                float s = sDot[row] + sDot[E_TE + row];
                int r = sRow[row];
                red_add_f(&g_dx[r * 3 + 0], sCD[row * 3 + 0] * s);
                red_add_f(&g_dx[r * 3 + 1], sCD[row * 3 + 1] * s);
                red_add_f(&g_dx[r * 3 + 2], sCD[row * 3 + 2] * s);
            }
        }
        __syncthreads();   // protect sIn/sM/scalars before next staging
    }
}

// ---------------------------------------------------------------------------
// Node kernel: h = (h + MLP([h|agg])) * mask ; x = (x + dx) * mask
// ---------------------------------------------------------------------------
#define N_TE 64
#define N_NS 132
#define N_SP 68
#define NOFF_W1  0
#define NOFF_B1  (NOFF_W1 + 128 * 64)
#define NOFF_W2  (NOFF_B1 + 64)
#define NOFF_B2  (NOFF_W2 + 4096)
#define NOFF_IN  (NOFF_B2 + 64)
#define NOFF_M1  (NOFF_IN + N_TE * N_NS)
#define NOFF_MK  (NOFF_M1 + N_TE * N_SP)
#define NODE_SMEM_FLOATS (NOFF_MK + N_TE)
#define NODE_SMEM_BYTES  (NODE_SMEM_FLOATS * 4)
#define N_TILES ((NN + N_TE - 1) / N_TE)

__global__ void __launch_bounds__(256, 2)
node_kernel(const float* __restrict__ W1, const float* __restrict__ b1,
            const float* __restrict__ W2, const float* __restrict__ b2,
            const float* __restrict__ node_mask) {
    extern __shared__ float sm[];
    float* sW1 = sm + NOFF_W1;
    float* sB1 = sm + NOFF_B1;
    float* sW2 = sm + NOFF_W2;
    float* sB2 = sm + NOFF_B2;
    float* sIn = sm + NOFF_IN;
    float* sM1 = sm + NOFF_M1;
    float* sMk = sm + NOFF_MK;

    const int tid = threadIdx.x;
    for (int idx = tid; idx < 128 * 64; idx += 256) sW1[idx] = W1[idx];
    for (int idx = tid; idx < 4096; idx += 256)     sW2[idx] = W2[idx];
    if (tid < 64) { sB1[tid] = b1[tid]; sB2[tid] = b2[tid]; }
    __syncthreads();

    const int jc = tid & 15;
    const int nr = tid >> 4;
    const int j0 = jc * 4;
    const int nb = nr * 4;

    const unsigned long long b1p0 = pack2(sB1[j0], sB1[j0 + 1]);
    const unsigned long long b1p1 = pack2(sB1[j0 + 2], sB1[j0 + 3]);
    const unsigned long long b2p0 = pack2(sB2[j0], sB2[j0 + 1]);
    const unsigned long long b2p1 = pack2(sB2[j0 + 2], sB2[j0 + 3]);

    for (int tile = blockIdx.x; tile < N_TILES; tile += gridDim.x) {
        const int n0 = tile * N_TE;
        const bool full = (n0 + N_TE <= NN);

        if (full) {
            for (int idx = tid; idx < N_TE * 16; idx += 256) {
                int nl = idx >> 4, j4 = (idx & 15) * 4;
                int n = n0 + nl;
                float4 hv = *(const float4*)(&g_h[n * 64 + j4]);
                float4 av = *(const float4*)(&g_agg[n * 64 + j4]);
                *(float4*)(sIn + nl * N_NS + j4)      = hv;
                *(float4*)(sIn + nl * N_NS + 64 + j4) = av;
            }
        } else {
            for (int idx = tid; idx < N_TE * 64; idx += 256) {
                int nl = idx >> 6, j = idx & 63;
                int n = n0 + nl;
                float hv = 0.0f, av = 0.0f;
                if (n < NN) { hv = g_h[n * 64 + j]; av = g_agg[n * 64 + j]; }
                sIn[nl * N_NS + j]      = hv;
                sIn[nl * N_NS + 64 + j] = av;
            }
        }
        if (tid < N_TE) {
            int n = n0 + tid;
            sMk[tid] = (n < NN) ? node_mask[n] : 0.0f;
        }
        __syncthreads();

        unsigned long long acc[4][2];
        #pragma unroll
        for (int e = 0; e < 4; e++) { acc[e][0] = b1p0; acc[e][1] = b1p1; }
        #pragma unroll 2
        for (int k = 0; k < 128; k += 4) {
            float4 v4[4];
            #pragma unroll
            for (int e = 0; e < 4; e++)
                v4[e] = *(const float4*)(sIn + (nb + e) * N_NS + k);
            #pragma unroll
            for (int kk = 0; kk < 4; kk++) {
                ulonglong2 w = *(const ulonglong2*)(sW1 + (k + kk) * 64 + j0);
                #pragma unroll
                for (int e = 0; e < 4; e++) {
                    float v = ((const float*)&v4[e])[kk];
                    unsigned long long vv = pack2(v, v);
                    ffma2(acc[e][0], vv, w.x);
                    ffma2(acc[e][1], vv, w.y);
                }
            }
        }
        #pragma unroll
        for (int e = 0; e < 4; e++) {
            float a0, a1, a2, a3;
            unpack2(acc[e][0], a0, a1);
            unpack2(acc[e][1], a2, a3);
            float4 o;
            o.x = silu_f(a0); o.y = silu_f(a1);
            o.z = silu_f(a2); o.w = silu_f(a3);
            *(float4*)(sM1 + (nb + e) * N_SP + j0) = o;
        }
        __syncthreads();

        #pragma unroll
        for (int e = 0; e < 4; e++) { acc[e][0] = b2p0; acc[e][1] = b2p1; }
        #pragma unroll 2
        for (int k = 0; k < 64; k += 4) {
            float4 v4[4];
            #pragma unroll
            for (int e = 0; e < 4; e++)
                v4[e] = *(const float4*)(sM1 + (nb + e) * N_SP + k);
            #pragma unroll
            for (int kk = 0; kk < 4; kk++) {
                ulonglong2 w = *(const ulonglong2*)(sW2 + (k + kk) * 64 + j0);
                #pragma unroll
                for (int e = 0; e < 4; e++) {
                    float v = ((const float*)&v4[e])[kk];
                    unsigned long long vv = pack2(v, v);
                    ffma2(acc[e][0], vv, w.x);
                    ffma2(acc[e][1], vv, w.y);
                }
            }
        }
        #pragma unroll
        for (int e = 0; e < 4; e++) {
            int n = n0 + nb + e;
            if (n < NN) {
                float a0, a1, a2, a3;
                unpack2(acc[e][0], a0, a1);
                unpack2(acc[e][1], a2, a3);
                float mk = sMk[nb + e];
                float4 o;
                o.x = (sIn[(nb + e) * N_NS + j0 + 0] + a0) * mk;
                o.y = (sIn[(nb + e) * N_NS + j0 + 1] + a1) * mk;
                o.z = (sIn[(nb + e) * N_NS + j0 + 2] + a2) * mk;
                o.w = (sIn[(nb + e) * N_NS + j0 + 3] + a3) * mk;
                *(float4*)(&g_h[n * 64 + j0]) = o;
            }
        }
        // x update
        if (tid < N_TE * 3) {
            int n = n0 + tid / 3;
            int k = tid % 3;
            if (n < NN) {
                float mk = node_mask[n];
                g_x[n * 3 + k] = (g_x[n * 3 + k] + g_dx[n * 3 + k]) * mk;
            }
        }
        __syncthreads();
    }
}

// ---------------------------------------------------------------------------
// Output kernel (h and x; e handled by the last edge layer)
// ---------------------------------------------------------------------------
__global__ void out_h_x_kernel(const float* __restrict__ W,  // [64,16]
                               const float* __restrict__ b,
                               const float* __restrict__ node_mask,
                               float* __restrict__ out) {
    int i = blockIdx.x * blockDim.x + threadIdx.x;
    if (i < NN * 16) {
        int n = i >> 4, j = i & 15;
        float a = b[j];
        #pragma unroll 4
        for (int k4 = 0; k4 < 64; k4 += 4) {
            float4 h4 = *(const float4*)(&g_h[n * 64 + k4]);
            a += h4.x * W[(k4 + 0) * 16 + j];
            a += h4.y * W[(k4 + 1) * 16 + j];
            a += h4.z * W[(k4 + 2) * 16 + j];
            a += h4.w * W[(k4 + 3) * 16 + j];
        }
        out[i] = a * node_mask[n];
    }
    if (i < NN * 3) out[NN * 16 + i] = g_x[i];
}

// ---------------------------------------------------------------------------
// Launch
// ---------------------------------------------------------------------------
extern "C" void kernel_launch(void* const* d_in, const int* in_sizes, int n_in,
                              void* d_out, int out_size) {
    const float* h_in      = (const float*)d_in[0];
    const float* x_in      = (const float*)d_in[1];
    const float* edge_attr = (const float*)d_in[2];
    const float* node_mask = (const float*)d_in[3];
    const float* edge_mask = (const float*)d_in[4];
    const float* Wn_in     = (const float*)d_in[5];
    const float* bn_in     = (const float*)d_in[6];
    const float* Wn_out    = (const float*)d_in[7];
    const float* bn_out    = (const float*)d_in[8];
    const float* We_in     = (const float*)d_in[9];
    const float* be_in     = (const float*)d_in[10];
    const float* We_out    = (const float*)d_in[11];
    const float* be_out    = (const float*)d_in[12];
    const float* eW1       = (const float*)d_in[13];
    const float* eb1       = (const float*)d_in[14];
    const float* eW2       = (const float*)d_in[15];
    const float* eb2       = (const float*)d_in[16];
    const float* nW1       = (const float*)d_in[17];
    const float* nb1       = (const float*)d_in[18];
    const float* nW2       = (const float*)d_in[19];
    const float* nb2       = (const float*)d_in[20];
    const float* cW1       = (const float*)d_in[21];
    const float* cb1       = (const float*)d_in[22];
    const float* cW2       = (const float*)d_in[23];
    const int*   edge_index = (const int*)d_in[24];
    float* out = (float*)d_out;
    float* out_e = out + NN * 16 + NN * 3;

    cudaFuncSetAttribute(edge_kernel<0, 0>, cudaFuncAttributeMaxDynamicSharedMemorySize,
                         EDGE_SMEM_BYTES);
    cudaFuncSetAttribute(edge_kernel<1, 0>, cudaFuncAttributeMaxDynamicSharedMemorySize,
                         EDGE_SMEM_BYTES);
    cudaFuncSetAttribute(edge_kernel<0, 1>, cudaFuncAttributeMaxDynamicSharedMemorySize,
                         EDGE_SMEM_BYTES);
    cudaFuncSetAttribute(node_kernel, cudaFuncAttributeMaxDynamicSharedMemorySize,
                         NODE_SMEM_BYTES);
    cudaFuncSetAttribute(pab_kernel, cudaFuncAttributeMaxDynamicSharedMemorySize,
                         PAB_SMEM_BYTES);

    embed_node_kernel<<<(NN * HD + 255) / 256, 256>>>(h_in, Wn_in, bn_in, x_in);

    for (int l = 0; l < NL; l++) {
        pab_kernel<<<304, P_T, PAB_SMEM_BYTES>>>(eW1 + l * 193 * 64);
        if (l == 0) {
            edge_kernel<1, 0><<<304, E_T, EDGE_SMEM_BYTES>>>(
                edge_index, edge_mask,
                eW1 + l * 193 * 64, eb1 + l * 64,
                eW2 + l * 4096,     eb2 + l * 64,
                cW1 + l * 4096,     cb1 + l * 64,
                cW2 + l * 64,
                edge_attr, We_in, be_in, out_e);
        } else if (l == NL - 1) {
            edge_kernel<0, 1><<<304, E_T, EDGE_SMEM_BYTES>>>(
                edge_index, edge_mask,
                eW1 + l * 193 * 64, eb1 + l * 64,
                eW2 + l * 4096,     eb2 + l * 64,
                cW1 + l * 4096,     cb1 + l * 64,
                cW2 + l * 64,
                edge_attr, We_out, be_out, out_e);
        } else {
            edge_kernel<0, 0><<<304, E_T, EDGE_SMEM_BYTES>>>(
                edge_index, edge_mask,
                eW1 + l * 193 * 64, eb1 + l * 64,
                eW2 + l * 4096,     eb2 + l * 64,
                cW1 + l * 4096,     cb1 + l * 64,
                cW2 + l * 64,
                edge_attr, We_in, be_in, out_e);
        }
        node_kernel<<<304, 256, NODE_SMEM_BYTES>>>(
            nW1 + l * 128 * 64, nb1 + l * 64,
            nW2 + l * 4096,     nb2 + l * 64,
            node_mask);
    }

    out_h_x_kernel<<<(NN * 16 + 255) / 256, 256>>>(Wn_out, bn_out, node_mask, out);
}

// round 17
// speedup vs baseline: 1.0359x; 1.0030x over previous
#include <cuda_runtime.h>
#include <math.h>

#define NN 50000
#define NE 800000
#define HD 64
#define NL 4

// Persistent state between launches (device globals: allocation-free).
__device__ float g_h[NN * HD];     // current node embedding
__device__ float g_e[NE * HD];     // current edge feature / message
__device__ float g_x[NN * 3];      // current coordinates
__device__ float g_agg[NN * HD];   // per-layer message aggregation
__device__ float g_dx[NN * 3];     // per-layer coordinate delta
__device__ float g_pa[NN * HD];    // h @ W1[0:64]   (row-half projection)
__device__ float g_pb[NN * HD];    // h @ W1[64:128] (col-half projection)

__device__ __forceinline__ float silu_f(float v) {
    return v / (1.0f + __expf(-v));
}

// ---- packed f32x2 helpers (Blackwell dual-rate fp32 path) ----
__device__ __forceinline__ unsigned long long pack2(float lo, float hi) {
    unsigned long long r;
    asm("mov.b64 %0, {%1, %2};" : "=l"(r) : "f"(lo), "f"(hi));
    return r;
}
__device__ __forceinline__ void unpack2(unsigned long long v, float& lo, float& hi) {
    asm("mov.b64 {%0, %1}, %2;" : "=f"(lo), "=f"(hi) : "l"(v));
}
__device__ __forceinline__ void ffma2(unsigned long long& d,
                                      unsigned long long a,
                                      unsigned long long b) {
    asm("fma.rn.f32x2 %0, %1, %2, %0;" : "+l"(d) : "l"(a), "l"(b));
}
__device__ __forceinline__ void red_add_v4(float* p, float4 v) {
    asm volatile("red.global.add.v4.f32 [%0], {%1, %2, %3, %4};"
                 :: "l"(p), "f"(v.x), "f"(v.y), "f"(v.z), "f"(v.w) : "memory");
}
__device__ __forceinline__ void red_add_f(float* p, float v) {
    asm volatile("red.global.add.f32 [%0], %1;" :: "l"(p), "f"(v) : "memory");
}
__device__ __forceinline__ void pair_bar(int id) {
    asm volatile("bar.sync %0, 64;" :: "r"(id) : "memory");
}
__device__ __forceinline__ float4 ldcs4(const float* p) {
    return __ldcs((const float4*)p);
}
__device__ __forceinline__ void stcs4(float* p, float4 v) {
    __stcs((float4*)p, v);
}

// ---------------------------------------------------------------------------
// Embedding kernel (node only; edge embed fused into first edge layer)
// ---------------------------------------------------------------------------
__global__ void embed_node_kernel(const float* __restrict__ h_in,
                                  const float* __restrict__ W,   // [16,64]
                                  const float* __restrict__ b,
                                  const float* __restrict__ x_in) {
    int i = blockIdx.x * blockDim.x + threadIdx.x;
    if (i < NN * HD) {
        int n = i >> 6, j = i & 63;
        float a = b[j];
        #pragma unroll
        for (int k = 0; k < 16; k++)
            a += h_in[n * 16 + k] * W[k * 64 + j];
        g_h[i] = a;
    }
    if (i < NN * 3) g_x[i] = x_in[i];
}

// ---------------------------------------------------------------------------
// Per-layer node projections: g_pa = h @ W1[0:64], g_pb = h @ W1[64:128].
// Also zeroes g_agg / g_dx for this layer.
// ---------------------------------------------------------------------------
#define P_T   512
#define P_TE  64
#define P_HS  68
#define POFF_W 0                      // 64 k x 128 jj = 8192 floats
#define POFF_H 8192                   // 64 x 68
#define PAB_SMEM_FLOATS (POFF_H + P_TE * P_HS)
#define PAB_SMEM_BYTES  (PAB_SMEM_FLOATS * 4)
#define P_TILES ((NN + P_TE - 1) / P_TE)

__global__ void __launch_bounds__(P_T, 2)
pab_kernel(const float* __restrict__ W1) {
    extern __shared__ float sm[];
    float* sW = sm + POFF_W;
    float* sH = sm + POFF_H;
    const int tid = threadIdx.x;

    // zero the per-layer accumulators (grid-stride)
    for (int i = blockIdx.x * P_T + tid; i < NN * HD; i += gridDim.x * P_T)
        g_agg[i] = 0.0f;
    for (int i = blockIdx.x * P_T + tid; i < NN * 3; i += gridDim.x * P_T)
        g_dx[i] = 0.0f;

    for (int idx = tid; idx < 8192; idx += P_T) {
        int k = idx >> 7, jj = idx & 127;
        sW[idx] = (jj < 64) ? W1[k * 64 + jj] : W1[(64 + k) * 64 + (jj - 64)];
    }
    __syncthreads();

    const int jc = tid & 31;
    const int nr = tid >> 5;
    const int j0 = jc * 4;
    const int nb = nr * 4;

    for (int tile = blockIdx.x; tile < P_TILES; tile += gridDim.x) {
        const int n0 = tile * P_TE;
        for (int idx = tid; idx < P_TE * 16; idx += P_T) {
            int nl = idx >> 4, j4 = (idx & 15) * 4;
            int n = n0 + nl;
            float4 hv = make_float4(0.f, 0.f, 0.f, 0.f);
            if (n < NN) hv = *(const float4*)(&g_h[n * 64 + j4]);
            *(float4*)(sH + nl * P_HS + j4) = hv;
        }
        __syncthreads();

        unsigned long long acc[4][2];
        const unsigned long long z = pack2(0.f, 0.f);
        #pragma unroll
        for (int e = 0; e < 4; e++) { acc[e][0] = z; acc[e][1] = z; }
        #pragma unroll 2
        for (int k = 0; k < 64; k += 4) {
            float4 v4[4];
            #pragma unroll
            for (int e = 0; e < 4; e++)
                v4[e] = *(const float4*)(sH + (nb + e) * P_HS + k);
            #pragma unroll
            for (int kk = 0; kk < 4; kk++) {
                ulonglong2 w = *(const ulonglong2*)(sW + (k + kk) * 128 + j0);
                #pragma unroll
                for (int e = 0; e < 4; e++) {
                    float v = ((const float*)&v4[e])[kk];
                    unsigned long long vv = pack2(v, v);
                    ffma2(acc[e][0], vv, w.x);
                    ffma2(acc[e][1], vv, w.y);
                }
            }
        }
        #pragma unroll
        for (int e = 0; e < 4; e++) {
            int n = n0 + nb + e;
            if (n < NN) {
                float a0, a1, a2, a3;
                unpack2(acc[e][0], a0, a1);
                unpack2(acc[e][1], a2, a3);
                float4 o = make_float4(a0, a1, a2, a3);
                if (j0 < 64)
                    *(float4*)(&g_pa[n * 64 + j0]) = o;
                else
                    *(float4*)(&g_pb[n * 64 + (j0 - 64)]) = o;
            }
        }
        __syncthreads();
    }
}

// ---------------------------------------------------------------------------
// Edge kernel (per layer), templated:
//   FIRST: e features computed in-staging from edge_attr @ We_in + be_in
//   LAST:  e_out = (m @ We_out + be_out) * mask written to out; g_e skipped
// 64 edges/tile, 256 threads, 2 CTAs/SM. Streaming cache hints on g_e.
// ---------------------------------------------------------------------------
#define E_T    256
#define E_TE   64
#define E_SP   68

#define OFF_W1E  0
#define OFF_WR   (OFF_W1E + 4096)
#define OFF_B1   (OFF_WR + 64)
#define OFF_W2   (OFF_B1 + 64)
#define OFF_B2   (OFF_W2 + 4096)
#define OFF_CW1  (OFF_B2 + 64)
#define OFF_CB1  (OFF_CW1 + 4096)
#define OFF_CW2  (OFF_CB1 + 64)
#define OFF_WE   (OFF_CW2 + 64)      // 512: We_in (8x64) or We_out (64x8)
#define OFF_BE   (OFF_WE + 512)      // 64: be_in or be_out(8)
#define OFF_IN   (OFF_BE + 64)
#define OFF_M1   (OFF_IN + E_TE * E_SP)
#define OFF_CD   (OFF_M1 + E_TE * E_SP)
#define OFF_DOT  (OFF_CD + 3 * E_TE)
#define OFF_RAD  (OFF_DOT + 2 * E_TE)
#define OFF_MSK  (OFF_RAD + E_TE)
#define OFF_ROW  (OFF_MSK + E_TE)
#define OFF_COL  (OFF_ROW + E_TE)
#define EDGE_SMEM_FLOATS (OFF_COL + E_TE)
#define EDGE_SMEM_BYTES  (EDGE_SMEM_FLOATS * 4)

template <int FIRST, int LAST>
__global__ void __launch_bounds__(E_T, 2)
edge_kernel(const int* __restrict__ eidx,
            const float* __restrict__ edge_mask,
            const float* __restrict__ W1, const float* __restrict__ b1,
            const float* __restrict__ W2, const float* __restrict__ b2,
            const float* __restrict__ cw1, const float* __restrict__ cb1,
            const float* __restrict__ cw2,
            const float* __restrict__ ea,      // FIRST: edge_attr [E,8]
            const float* __restrict__ WeX,     // FIRST: We_in ; LAST: We_out
            const float* __restrict__ beX,     // FIRST: be_in ; LAST: be_out
            float* __restrict__ oute) {        // LAST: output e region [E,8]
    extern __shared__ float sm[];
    float* sW1E = sm + OFF_W1E;
    float* sWr  = sm + OFF_WR;
    float* sB1  = sm + OFF_B1;
    float* sW2  = sm + OFF_W2;
    float* sB2  = sm + OFF_B2;
    float* sCW1 = sm + OFF_CW1;
    float* sCB1 = sm + OFF_CB1;
    float* sCW2 = sm + OFF_CW2;
    float* sWE  = sm + OFF_WE;
    float* sBE  = sm + OFF_BE;
    float* sIn  = sm + OFF_IN;     // e features, stride 68
    float* sM1  = sm + OFF_M1;
    float* sM   = sm + OFF_IN;     // row-aligned alias of sIn (holds m)
    float* sCD  = sm + OFF_CD;
    float* sDot = sm + OFF_DOT;    // [2][64] half-dot exchange
    float* sRad = sm + OFF_RAD;
    float* sMsk = sm + OFF_MSK;
    int*   sRow = (int*)(sm + OFF_ROW);
    int*   sCol = (int*)(sm + OFF_COL);

    const int tid = threadIdx.x;

    // W1 rows: 0..63=h_row(->Pa), 64..127=h_col(->Pb), 128=radial, 129..192=e
    for (int idx = tid; idx < 4096; idx += E_T) {
        int k = idx >> 6, j = idx & 63;
        sW1E[idx] = W1[(129 + k) * 64 + j];
        sW2[idx]  = W2[idx];
        sCW1[idx] = cw1[idx];
    }
    if (tid < 64) {
        sWr[tid]  = W1[128 * 64 + tid];
        sB1[tid]  = b1[tid];
        sB2[tid]  = b2[tid];
        sCB1[tid] = cb1[tid];
        sCW2[tid] = cw2[tid];
    }
    if (FIRST || LAST) {
        for (int idx = tid; idx < 512; idx += E_T) sWE[idx] = WeX[idx];
        if (tid < 64) sBE[tid] = (FIRST || tid < 8) ? beX[tid] : 0.f;
    }
    __syncthreads();

    // warp covers one 32-col half of 16 edges; thread tile edges eb0 + 4*e
    const int warp = tid >> 5;
    const int lane = tid & 31;
    const int half = warp & 1;      // col half
    const int q    = warp >> 1;     // edge quarter (pair id)
    const int jc   = lane & 7;      // 8 col groups x 4
    const int erl  = lane >> 3;     // 4 consecutive base rows
    const int j0   = half * 32 + jc * 4;
    const int eb0  = q * 16 + erl;

    const float4 b1f  = *(const float4*)(sB1 + j0);
    const float4 wrf  = *(const float4*)(sWr + j0);
    const float4 cw2f = *(const float4*)(sCW2 + j0);
    const unsigned long long b2p0 = pack2(sB2[j0], sB2[j0 + 1]);
    const unsigned long long b2p1 = pack2(sB2[j0 + 2], sB2[j0 + 3]);
    const unsigned long long bcp0 = pack2(sCB1[j0], sCB1[j0 + 1]);
    const unsigned long long bcp1 = pack2(sCB1[j0 + 2], sCB1[j0 + 3]);

    const int NT = NE / E_TE;

    // ---- prologue prefetch for first tile ----
    int tile = blockIdx.x;
    int pr = 0, pc = 0;
    float pmsk = 0.f;
    float prx0 = 0.f, prx1 = 0.f, prx2 = 0.f;
    float pcx0 = 0.f, pcx1 = 0.f, pcx2 = 0.f;
    float4 pfe[4];
    if (tile < NT) {
        if (tid < E_TE) {
            int e = tile * E_TE + tid;
            pr = eidx[e]; pc = eidx[NE + e]; pmsk = edge_mask[e];
        }
        if (!FIRST) {
            #pragma unroll
            for (int s = 0; s < 4; s++) {
                int idx = tid + s * E_T;
                int el = idx >> 4, j4 = (idx & 15) * 4;
                pfe[s] = ldcs4(&g_e[(tile * E_TE + el) * 64 + j4]);
            }
        }
        if (tid < E_TE) {
            prx0 = g_x[pr * 3 + 0]; prx1 = g_x[pr * 3 + 1]; prx2 = g_x[pr * 3 + 2];
            pcx0 = g_x[pc * 3 + 0]; pcx1 = g_x[pc * 3 + 1]; pcx2 = g_x[pc * 3 + 2];
        }
    }

    for (; tile < NT; tile += gridDim.x) {
        const int e0 = tile * E_TE;

        // ---- consume prefetched tile state into smem ----
        if (tid < E_TE) {
            sRow[tid] = pr;
            sCol[tid] = pc;
            float dx = prx0 - pcx0;
            float dy = prx1 - pcx1;
            float dz = prx2 - pcx2;
            float rad = dx * dx + dy * dy + dz * dz;
            float inv = 1.0f / (sqrtf(rad) + 1.0f);
            sCD[tid * 3 + 0] = dx * inv;
            sCD[tid * 3 + 1] = dy * inv;
            sCD[tid * 3 + 2] = dz * inv;
            sRad[tid] = rad;
            sMsk[tid] = pmsk;
        }
        if (FIRST) {
            // e features computed from edge_attr on the fly (k=8 mini-GEMM)
            for (int idx = tid; idx < E_TE * 16; idx += E_T) {
                int el = idx >> 4, j4 = (idx & 15) * 4;
                const float* ear = ea + (size_t)(e0 + el) * 8;
                float4 a = *(const float4*)(sBE + j4);
                #pragma unroll
                for (int k = 0; k < 8; k++) {
                    float v = __ldg(ear + k);
                    float4 w = *(const float4*)(sWE + k * 64 + j4);
                    a.x += v * w.x; a.y += v * w.y;
                    a.z += v * w.z; a.w += v * w.w;
                }
                *(float4*)(sIn + el * E_SP + j4) = a;
            }
        } else {
            #pragma unroll
            for (int s = 0; s < 4; s++) {
                int idx = tid + s * E_T;
                int el = idx >> 4, j4 = (idx & 15) * 4;
                *(float4*)(sIn + el * E_SP + j4) = pfe[s];
            }
        }
        __syncthreads();

        // ---- issue next-tile prefetch (indices, mask, e-features) ----
        const int ntile = tile + gridDim.x;
        const bool hn = ntile < NT;
        if (hn) {
            if (tid < E_TE) {
                int e = ntile * E_TE + tid;
                pr = eidx[e]; pc = eidx[NE + e]; pmsk = edge_mask[e];
            }
            if (!FIRST) {
                #pragma unroll
                for (int s = 0; s < 4; s++) {
                    int idx = tid + s * E_T;
                    int el = idx >> 4, j4 = (idx & 15) * 4;
                    pfe[s] = ldcs4(&g_e[(ntile * E_TE + el) * 64 + j4]);
                }
            }
        }

        // ---- GEMM1: init from Pa/Pb (direct global) + rad, k=64 over e ----
        unsigned long long acc[4][2];
        #pragma unroll
        for (int e = 0; e < 4; e++) {
            int row = eb0 + 4 * e;
            float4 pa = *(const float4*)(&g_pa[sRow[row] * 64 + j0]);
            float4 pb = *(const float4*)(&g_pb[sCol[row] * 64 + j0]);
            float rad = sRad[row];
            float f0 = b1f.x + pa.x + pb.x + rad * wrf.x;
            float f1 = b1f.y + pa.y + pb.y + rad * wrf.y;
            float f2 = b1f.z + pa.z + pb.z + rad * wrf.z;
            float f3 = b1f.w + pa.w + pb.w + rad * wrf.w;
            acc[e][0] = pack2(f0, f1);
            acc[e][1] = pack2(f2, f3);
        }
        #pragma unroll 2
        for (int k = 0; k < 64; k += 4) {
            float4 v4[4];
            #pragma unroll
            for (int e = 0; e < 4; e++)
                v4[e] = *(const float4*)(sIn + (eb0 + 4 * e) * E_SP + k);
            #pragma unroll
            for (int kk = 0; kk < 4; kk++) {
                ulonglong2 w = *(const ulonglong2*)(sW1E + (k + kk) * 64 + j0);
                #pragma unroll
                for (int e = 0; e < 4; e++) {
                    float v = ((const float*)&v4[e])[kk];
                    unsigned long long vv = pack2(v, v);
                    ffma2(acc[e][0], vv, w.x);
                    ffma2(acc[e][1], vv, w.y);
                }
            }
        }
        #pragma unroll
        for (int e = 0; e < 4; e++) {
            float a0, a1, a2, a3;
            unpack2(acc[e][0], a0, a1);
            unpack2(acc[e][1], a2, a3);
            float4 o;
            o.x = silu_f(a0); o.y = silu_f(a1);
            o.z = silu_f(a2); o.w = silu_f(a3);
            *(float4*)(sM1 + (eb0 + 4 * e) * E_SP + j0) = o;
        }
        pair_bar(1 + q);   // pair done with GEMM1 (sIn rows consumed)

        // ---- dependent coord prefetch (pr/pc arrived during GEMM1) ----
        if (hn && tid < E_TE) {
            prx0 = g_x[pr * 3 + 0]; prx1 = g_x[pr * 3 + 1]; prx2 = g_x[pr * 3 + 2];
            pcx0 = g_x[pc * 3 + 0]; pcx1 = g_x[pc * 3 + 1]; pcx2 = g_x[pc * 3 + 2];
        }

        // ---- GEMM2: m = silu(m1 @ W2 + b2) * mask ----
        #pragma unroll
        for (int e = 0; e < 4; e++) { acc[e][0] = b2p0; acc[e][1] = b2p1; }
        #pragma unroll 2
        for (int k = 0; k < 64; k += 4) {
            float4 v4[4];
            #pragma unroll
            for (int e = 0; e < 4; e++)
                v4[e] = *(const float4*)(sM1 + (eb0 + 4 * e) * E_SP + k);
            #pragma unroll
            for (int kk = 0; kk < 4; kk++) {
                ulonglong2 w = *(const ulonglong2*)(sW2 + (k + kk) * 64 + j0);
                #pragma unroll
                for (int e = 0; e < 4; e++) {
                    float v = ((const float*)&v4[e])[kk];
                    unsigned long long vv = pack2(v, v);
                    ffma2(acc[e][0], vv, w.x);
                    ffma2(acc[e][1], vv, w.y);
                }
            }
        }
        #pragma unroll
        for (int e = 0; e < 4; e++) {
            int row = eb0 + 4 * e;
            float a0, a1, a2, a3;
            unpack2(acc[e][0], a0, a1);
            unpack2(acc[e][1], a2, a3);
            float mk = sMsk[row];
            float4 o;
            o.x = silu_f(a0) * mk; o.y = silu_f(a1) * mk;
            o.z = silu_f(a2) * mk; o.w = silu_f(a3) * mk;
            *(float4*)(sM + row * E_SP + j0) = o;
            if (!LAST)
                stcs4(&g_e[(e0 + row) * 64 + j0], o);
            red_add_v4(&g_agg[sRow[row] * 64 + j0], o);
        }
        pair_bar(1 + q);   // m complete for this pair's edges

        if (LAST) {
            // all pairs' m needed for the e_out tile below
            __syncthreads();
            #pragma unroll
            for (int t = 0; t < 2; t++) {
                int idx = tid * 2 + t;          // 0..511
                int el = idx >> 3, p = idx & 7;
                float a = 0.f;
                #pragma unroll 4
                for (int k4 = 0; k4 < 64; k4 += 4) {
                    float4 mv = *(const float4*)(sM + el * E_SP + k4);
                    a += mv.x * sWE[(k4 + 0) * 8 + p];
                    a += mv.y * sWE[(k4 + 1) * 8 + p];
                    a += mv.z * sWE[(k4 + 2) * 8 + p];
                    a += mv.w * sWE[(k4 + 3) * 8 + p];
                }
                oute[(size_t)(e0 + el) * 8 + p] = (a + sBE[p]) * sMsk[el];
            }
        }

        // ---- GEMM3 (coord hidden) + register dot with cW2 ----
        #pragma unroll
        for (int e = 0; e < 4; e++) { acc[e][0] = bcp0; acc[e][1] = bcp1; }
        #pragma unroll 2
        for (int k = 0; k < 64; k += 4) {
            float4 v4[4];
            #pragma unroll
            for (int e = 0; e < 4; e++)
                v4[e] = *(const float4*)(sM + (eb0 + 4 * e) * E_SP + k);
            #pragma unroll
            for (int kk = 0; kk < 4; kk++) {
                ulonglong2 w = *(const ulonglong2*)(sCW1 + (k + kk) * 64 + j0);
                #pragma unroll
                for (int e = 0; e < 4; e++) {
                    float v = ((const float*)&v4[e])[kk];
                    unsigned long long vv = pack2(v, v);
                    ffma2(acc[e][0], vv, w.x);
                    ffma2(acc[e][1], vv, w.y);
                }
            }
        }
        float part[4];
        #pragma unroll
        for (int e = 0; e < 4; e++) {
            float a0, a1, a2, a3;
            unpack2(acc[e][0], a0, a1);
            unpack2(acc[e][1], a2, a3);
            part[e] = silu_f(a0) * cw2f.x + silu_f(a1) * cw2f.y
                    + silu_f(a2) * cw2f.z + silu_f(a3) * cw2f.w;
        }
        // reduce over the 8 jc lanes (lane bits 0..2)
        #pragma unroll
        for (int e = 0; e < 4; e++) {
            part[e] += __shfl_xor_sync(0xffffffffu, part[e], 1);
            part[e] += __shfl_xor_sync(0xffffffffu, part[e], 2);
            part[e] += __shfl_xor_sync(0xffffffffu, part[e], 4);
        }
        if (jc == 0) {
            #pragma unroll
            for (int e = 0; e < 4; e++)
                sDot[half * E_TE + eb0 + 4 * e] = part[e];
        }
        pair_bar(1 + q);   // both halves' partial dots visible
        if (half == 0 && jc == 0) {
            #pragma unroll
            for (int e = 0; e < 4; e++) {
                int row = eb0 + 4 * e;
                float s = sDot[row] + sDot[E_TE + row];
                int r = sRow[row];
                red_add_f(&g_dx[r * 3 + 0], sCD[row * 3 + 0] * s);
                red_add_f(&g_dx[r * 3 + 1], sCD[row * 3 + 1] * s);
                red_add_f(&g_dx[r * 3 + 2], sCD[row * 3 + 2] * s);
            }
        }
        __syncthreads();   // protect sIn/sM/scalars before next staging
    }
}

// ---------------------------------------------------------------------------
// Node kernel: h = (h + MLP([h|agg])) * mask ; x = (x + dx) * mask
// LAST: fused output head — out_h = h@Wn_out+bn_out, out_x = x; skips g_h.
// ---------------------------------------------------------------------------
#define N_TE 64
#define N_NS 132
#define N_SP 68
#define NOFF_W1  0
#define NOFF_B1  (NOFF_W1 + 128 * 64)
#define NOFF_W2  (NOFF_B1 + 64)
#define NOFF_B2  (NOFF_W2 + 4096)
#define NOFF_WO  (NOFF_B2 + 64)        // 1024: Wn_out [64,16]
#define NOFF_BO  (NOFF_WO + 1024)      // 16
#define NOFF_IN  (NOFF_BO + 16)
#define NOFF_M1  (NOFF_IN + N_TE * N_NS)
#define NOFF_MK  (NOFF_M1 + N_TE * N_SP)
#define NODE_SMEM_FLOATS (NOFF_MK + N_TE)
#define NODE_SMEM_BYTES  (NODE_SMEM_FLOATS * 4)
#define N_TILES ((NN + N_TE - 1) / N_TE)

template <int LASTL>
__global__ void __launch_bounds__(256, 2)
node_kernel(const float* __restrict__ W1, const float* __restrict__ b1,
            const float* __restrict__ W2, const float* __restrict__ b2,
            const float* __restrict__ node_mask,
            const float* __restrict__ Wo, const float* __restrict__ bo,
            float* __restrict__ out) {
    extern __shared__ float sm[];
    float* sW1 = sm + NOFF_W1;
    float* sB1 = sm + NOFF_B1;
    float* sW2 = sm + NOFF_W2;
    float* sB2 = sm + NOFF_B2;
    float* sWo = sm + NOFF_WO;
    float* sBo = sm + NOFF_BO;
    float* sIn = sm + NOFF_IN;
    float* sM1 = sm + NOFF_M1;
    float* sMk = sm + NOFF_MK;

    const int tid = threadIdx.x;
    for (int idx = tid; idx < 128 * 64; idx += 256) sW1[idx] = W1[idx];
    for (int idx = tid; idx < 4096; idx += 256)     sW2[idx] = W2[idx];
    if (tid < 64) { sB1[tid] = b1[tid]; sB2[tid] = b2[tid]; }
    if (LASTL) {
        for (int idx = tid; idx < 1024; idx += 256) sWo[idx] = Wo[idx];
        if (tid < 16) sBo[tid] = bo[tid];
    }
    __syncthreads();

    const int jc = tid & 15;
    const int nr = tid >> 4;
    const int j0 = jc * 4;
    const int nb = nr * 4;

    const unsigned long long b1p0 = pack2(sB1[j0], sB1[j0 + 1]);
    const unsigned long long b1p1 = pack2(sB1[j0 + 2], sB1[j0 + 3]);
    const unsigned long long b2p0 = pack2(sB2[j0], sB2[j0 + 1]);
    const unsigned long long b2p1 = pack2(sB2[j0 + 2], sB2[j0 + 3]);

    for (int tile = blockIdx.x; tile < N_TILES; tile += gridDim.x) {
        const int n0 = tile * N_TE;
        const bool full = (n0 + N_TE <= NN);

        if (full) {
            for (int idx = tid; idx < N_TE * 16; idx += 256) {
                int nl = idx >> 4, j4 = (idx & 15) * 4;
                int n = n0 + nl;
                float4 hv = *(const float4*)(&g_h[n * 64 + j4]);
                float4 av = *(const float4*)(&g_agg[n * 64 + j4]);
                *(float4*)(sIn + nl * N_NS + j4)      = hv;
                *(float4*)(sIn + nl * N_NS + 64 + j4) = av;
            }
        } else {
            for (int idx = tid; idx < N_TE * 64; idx += 256) {
                int nl = idx >> 6, j = idx & 63;
                int n = n0 + nl;
                float hv = 0.0f, av = 0.0f;
                if (n < NN) { hv = g_h[n * 64 + j]; av = g_agg[n * 64 + j]; }
                sIn[nl * N_NS + j]      = hv;
                sIn[nl * N_NS + 64 + j] = av;
            }
        }
        if (tid < N_TE) {
            int n = n0 + tid;
            sMk[tid] = (n < NN) ? node_mask[n] : 0.0f;
        }
        __syncthreads();

        unsigned long long acc[4][2];
        #pragma unroll
        for (int e = 0; e < 4; e++) { acc[e][0] = b1p0; acc[e][1] = b1p1; }
        #pragma unroll 2
        for (int k = 0; k < 128; k += 4) {
            float4 v4[4];
            #pragma unroll
            for (int e = 0; e < 4; e++)
                v4[e] = *(const float4*)(sIn + (nb + e) * N_NS + k);
            #pragma unroll
            for (int kk = 0; kk < 4; kk++) {
                ulonglong2 w = *(const ulonglong2*)(sW1 + (k + kk) * 64 + j0);
                #pragma unroll
                for (int e = 0; e < 4; e++) {
                    float v = ((const float*)&v4[e])[kk];
                    unsigned long long vv = pack2(v, v);
                    ffma2(acc[e][0], vv, w.x);
                    ffma2(acc[e][1], vv, w.y);
                }
            }
        }
        #pragma unroll
        for (int e = 0; e < 4; e++) {
            float a0, a1, a2, a3;
            unpack2(acc[e][0], a0, a1);
            unpack2(acc[e][1], a2, a3);
            float4 o;
            o.x = silu_f(a0); o.y = silu_f(a1);
            o.z = silu_f(a2); o.w = silu_f(a3);
            *(float4*)(sM1 + (nb + e) * N_SP + j0) = o;
        }
        __syncthreads();

        #pragma unroll
        for (int e = 0; e < 4; e++) { acc[e][0] = b2p0; acc[e][1] = b2p1; }
        #pragma unroll 2
        for (int k = 0; k < 64; k += 4) {
            float4 v4[4];
            #pragma unroll
            for (int e = 0; e < 4; e++)
                v4[e] = *(const float4*)(sM1 + (nb + e) * N_SP + k);
            #pragma unroll
            for (int kk = 0; kk < 4; kk++) {
                ulonglong2 w = *(const ulonglong2*)(sW2 + (k + kk) * 64 + j0);
                #pragma unroll
                for (int e = 0; e < 4; e++) {
                    float v = ((const float*)&v4[e])[kk];
                    unsigned long long vv = pack2(v, v);
                    ffma2(acc[e][0], vv, w.x);
                    ffma2(acc[e][1], vv, w.y);
                }
            }
        }
        #pragma unroll
        for (int e = 0; e < 4; e++) {
            int n = n0 + nb + e;
            if (n < NN) {
                float a0, a1, a2, a3;
                unpack2(acc[e][0], a0, a1);
                unpack2(acc[e][1], a2, a3);
                float mk = sMk[nb + e];
                float4 o;
                o.x = (sIn[(nb + e) * N_NS + j0 + 0] + a0) * mk;
                o.y = (sIn[(nb + e) * N_NS + j0 + 1] + a1) * mk;
                o.z = (sIn[(nb + e) * N_NS + j0 + 2] + a2) * mk;
                o.w = (sIn[(nb + e) * N_NS + j0 + 3] + a3) * mk;
                if (LASTL)
                    *(float4*)(sIn + (nb + e) * N_NS + j0) = o;  // own slots
                else
                    *(float4*)(&g_h[n * 64 + j0]) = o;
            }
        }
        // x update
        if (tid < N_TE * 3) {
            int n = n0 + tid / 3;
            int k = tid % 3;
            if (n < NN) {
                float mk = node_mask[n];
                float xv = (g_x[n * 3 + k] + g_dx[n * 3 + k]) * mk;
                if (LASTL)
                    out[NN * 16 + n * 3 + k] = xv;
                else
                    g_x[n * 3 + k] = xv;
            }
        }
        if (LASTL) {
            __syncthreads();   // h_final complete in sIn
            // out_h: 64 nodes x 16 outputs = 1024 elems, 4 per thread
            int nl = tid >> 2, p4 = (tid & 3) * 4;
            int n = n0 + nl;
            if (n < NN) {
                float a0 = sBo[p4], a1 = sBo[p4 + 1];
                float a2 = sBo[p4 + 2], a3 = sBo[p4 + 3];
                #pragma unroll 4
                for (int k4 = 0; k4 < 64; k4 += 4) {
                    float4 hv = *(const float4*)(sIn + nl * N_NS + k4);
                    a0 += hv.x * sWo[(k4 + 0) * 16 + p4]
                        + hv.y * sWo[(k4 + 1) * 16 + p4]
                        + hv.z * sWo[(k4 + 2) * 16 + p4]
                        + hv.w * sWo[(k4 + 3) * 16 + p4];
                    a1 += hv.x * sWo[(k4 + 0) * 16 + p4 + 1]
                        + hv.y * sWo[(k4 + 1) * 16 + p4 + 1]
                        + hv.z * sWo[(k4 + 2) * 16 + p4 + 1]
                        + hv.w * sWo[(k4 + 3) * 16 + p4 + 1];
                    a2 += hv.x * sWo[(k4 + 0) * 16 + p4 + 2]
                        + hv.y * sWo[(k4 + 1) * 16 + p4 + 2]
                        + hv.z * sWo[(k4 + 2) * 16 + p4 + 2]
                        + hv.w * sWo[(k4 + 3) * 16 + p4 + 2];
                    a3 += hv.x * sWo[(k4 + 0) * 16 + p4 + 3]
                        + hv.y * sWo[(k4 + 1) * 16 + p4 + 3]
                        + hv.z * sWo[(k4 + 2) * 16 + p4 + 3]
                        + hv.w * sWo[(k4 + 3) * 16 + p4 + 3];
                }
                float mk = sMk[nl];
                float4 o = make_float4(a0 * mk, a1 * mk, a2 * mk, a3 * mk);
                *(float4*)(&out[n * 16 + p4]) = o;
            }
        }
        __syncthreads();
    }
}

// ---------------------------------------------------------------------------
// Launch
// ---------------------------------------------------------------------------
extern "C" void kernel_launch(void* const* d_in, const int* in_sizes, int n_in,
                              void* d_out, int out_size) {
    const float* h_in      = (const float*)d_in[0];
    const float* x_in      = (const float*)d_in[1];
    const float* edge_attr = (const float*)d_in[2];
    const float* node_mask = (const float*)d_in[3];
    const float* edge_mask = (const float*)d_in[4];
    const float* Wn_in     = (const float*)d_in[5];
    const float* bn_in     = (const float*)d_in[6];
    const float* Wn_out    = (const float*)d_in[7];
    const float* bn_out    = (const float*)d_in[8];
    const float* We_in     = (const float*)d_in[9];
    const float* be_in     = (const float*)d_in[10];
    const float* We_out    = (const float*)d_in[11];
    const float* be_out    = (const float*)d_in[12];
    const float* eW1       = (const float*)d_in[13];
    const float* eb1       = (const float*)d_in[14];
    const float* eW2       = (const float*)d_in[15];
    const float* eb2       = (const float*)d_in[16];
    const float* nW1       = (const float*)d_in[17];
    const float* nb1       = (const float*)d_in[18];
    const float* nW2       = (const float*)d_in[19];
    const float* nb2       = (const float*)d_in[20];
    const float* cW1       = (const float*)d_in[21];
    const float* cb1       = (const float*)d_in[22];
    const float* cW2       = (const float*)d_in[23];
    const int*   edge_index = (const int*)d_in[24];
    float* out = (float*)d_out;
    float* out_e = out + NN * 16 + NN * 3;

    cudaFuncSetAttribute(edge_kernel<0, 0>, cudaFuncAttributeMaxDynamicSharedMemorySize,
                         EDGE_SMEM_BYTES);
    cudaFuncSetAttribute(edge_kernel<1, 0>, cudaFuncAttributeMaxDynamicSharedMemorySize,
                         EDGE_SMEM_BYTES);
    cudaFuncSetAttribute(edge_kernel<0, 1>, cudaFuncAttributeMaxDynamicSharedMemorySize,
                         EDGE_SMEM_BYTES);
    cudaFuncSetAttribute(node_kernel<0>, cudaFuncAttributeMaxDynamicSharedMemorySize,
                         NODE_SMEM_BYTES);
    cudaFuncSetAttribute(node_kernel<1>, cudaFuncAttributeMaxDynamicSharedMemorySize,
                         NODE_SMEM_BYTES);
    cudaFuncSetAttribute(pab_kernel, cudaFuncAttributeMaxDynamicSharedMemorySize,
                         PAB_SMEM_BYTES);

    embed_node_kernel<<<(NN * HD + 255) / 256, 256>>>(h_in, Wn_in, bn_in, x_in);

    for (int l = 0; l < NL; l++) {
        pab_kernel<<<304, P_T, PAB_SMEM_BYTES>>>(eW1 + l * 193 * 64);
        if (l == 0) {
            edge_kernel<1, 0><<<304, E_T, EDGE_SMEM_BYTES>>>(
                edge_index, edge_mask,
                eW1 + l * 193 * 64, eb1 + l * 64,
                eW2 + l * 4096,     eb2 + l * 64,
                cW1 + l * 4096,     cb1 + l * 64,
                cW2 + l * 64,
                edge_attr, We_in, be_in, out_e);
        } else if (l == NL - 1) {
            edge_kernel<0, 1><<<304, E_T, EDGE_SMEM_BYTES>>>(
                edge_index, edge_mask,
                eW1 + l * 193 * 64, eb1 + l * 64,
                eW2 + l * 4096,     eb2 + l * 64,
                cW1 + l * 4096,     cb1 + l * 64,
                cW2 + l * 64,
                edge_attr, We_out, be_out, out_e);
        } else {
            edge_kernel<0, 0><<<304, E_T, EDGE_SMEM_BYTES>>>(
                edge_index, edge_mask,
                eW1 + l * 193 * 64, eb1 + l * 64,
                eW2 + l * 4096,     eb2 + l * 64,
                cW1 + l * 4096,     cb1 + l * 64,
                cW2 + l * 64,
                edge_attr, We_in, be_in, out_e);
        }
        if (l == NL - 1) {
            node_kernel<1><<<304, 256, NODE_SMEM_BYTES>>>(
                nW1 + l * 128 * 64, nb1 + l * 64,
                nW2 + l * 4096,     nb2 + l * 64,
                node_mask, Wn_out, bn_out, out);
        } else {
            node_kernel<0><<<304, 256, NODE_SMEM_BYTES>>>(
                nW1 + l * 128 * 64, nb1 + l * 64,
                nW2 + l * 4096,     nb2 + l * 64,
                node_mask, Wn_out, bn_out, out);
        }
    }
}